// round 10
// baseline (speedup 1.0000x reference)
#include <cuda_runtime.h>
#include <cuda_bf16.h>

#define LL     1024
#define SSQ    1024
#define MMEM   256
#define NBATCH 8
#define EDIM   512
#define NHEAD  8
#define HDIM   64
#define NH     64        // NBATCH * NHEAD
#define RTOT   8192      // LL * NBATCH

// ---------------- device-global scratch (the only legal scratch) -----------
static __device__ float g_q[NH * LL * HDIM];               // [nh][l][d]
static __device__ float g_k[NH * SSQ * HDIM];              // [nh][s][d]
static __device__ float g_v[NH * SSQ * HDIM];              // [nh][s][d]
static __device__ float g_sc[(size_t)NH * LL * SSQ];       // exp(scores) 256MB
static __device__ float g_csum[NH * SSQ];                  // column sums
static __device__ float g_attn[NH * LL * HDIM];            // main-branch attn
static __device__ float g_ctx[(size_t)RTOT * EDIM];        // [l*8+n][e]
static __device__ unsigned char g_mask[NBATCH * MMEM];     // decoded bool mask

__device__ __forceinline__ float warp_sum32(float x) {
    x += __shfl_xor_sync(0xffffffffu, x, 16);
    x += __shfl_xor_sync(0xffffffffu, x, 8);
    x += __shfl_xor_sync(0xffffffffu, x, 4);
    x += __shfl_xor_sync(0xffffffffu, x, 2);
    x += __shfl_xor_sync(0xffffffffu, x, 1);
    return x;
}

// ============================================================================
// K0: decode mem_mask regardless of upload encoding (uint8 / int32 / float32 /
// bf16). Sniff encoding from the first 512 words (2048 bytes — safe for all).
// ============================================================================
__global__ __launch_bounds__(256) void mask_decode_kernel(
    const unsigned int* __restrict__ m)
{
    __shared__ int enc_flags;   // bit0: 1-byte packed, bit1: bf16
    if (threadIdx.x == 0) enc_flags = 0;
    __syncthreads();
    for (int i = threadIdx.x; i < 512; i += 256) {
        unsigned int w = m[i];
        if ((w & 0xFFFFu) == 0x3F80u) atomicOr(&enc_flags, 2);        // bf16
        else if ((w >> 8) != 0 && w != 0x3F800000u) atomicOr(&enc_flags, 1);
    }
    __syncthreads();
    int f = enc_flags;
    if (f & 2) {            // bfloat16: halfword per element
        const unsigned short* mh = (const unsigned short*)m;
        for (int i = threadIdx.x; i < NBATCH * MMEM; i += 256)
            g_mask[i] = mh[i] ? 1 : 0;
    } else if (f & 1) {     // packed 1-byte (numpy bool_)
        const unsigned char* mb = (const unsigned char*)m;
        for (int i = threadIdx.x; i < NBATCH * MMEM; i += 256)
            g_mask[i] = mb[i] ? 1 : 0;
    } else {                // 4-byte: int32 {0,1} or float32 {0.0,1.0}
        for (int i = threadIdx.x; i < NBATCH * MMEM; i += 256)
            g_mask[i] = m[i] ? 1 : 0;
    }
}

// ============================================================================
// K1: fused QKV projection + bias + q-scale + rotary.  Out: [nh][l|s][d].
// 128x128x8 SGEMM tile, 256 threads, 8x8 microtile. blockIdx.z = {q,k,v}.
// ============================================================================
__global__ __launch_bounds__(256) void qkv_kernel(
    const float* __restrict__ Xq, const float* __restrict__ Xk,
    const float* __restrict__ Xv, const float* __restrict__ W,
    const float* __restrict__ Bb, const float* __restrict__ rq,
    const float* __restrict__ rk)
{
    const int mode = blockIdx.z;  // 0=q, 1=k, 2=v
    const float* X   = (mode == 0) ? Xq : (mode == 1) ? Xk : Xv;
    const float* Wm  = W + (size_t)mode * EDIM * EDIM;
    const float* Bm  = Bb + mode * EDIM;
    const float* rot = (mode == 0) ? rq : rk;
    float* dst = (mode == 0) ? g_q : (mode == 1) ? g_k : g_v;

    __shared__ float As[8][132];
    __shared__ float Bs[8][132];

    const int t = threadIdx.x;
    const int row0 = blockIdx.y * 128;
    const int col0 = blockIdx.x * 128;
    const int lrow = t >> 1;
    const int lk = (t & 1) * 4;
    const int ty = t >> 4;
    const int tx = t & 15;

    float acc[8][8] = {};

    const float* Ap = X + (size_t)(row0 + lrow) * EDIM + lk;
    const float* Bp = Wm + (size_t)(col0 + lrow) * EDIM + lk;

    for (int k0 = 0; k0 < EDIM; k0 += 8) {
        float4 av = *(const float4*)(Ap + k0);
        float4 bv = *(const float4*)(Bp + k0);
        __syncthreads();
        As[lk + 0][lrow] = av.x; As[lk + 1][lrow] = av.y;
        As[lk + 2][lrow] = av.z; As[lk + 3][lrow] = av.w;
        Bs[lk + 0][lrow] = bv.x; Bs[lk + 1][lrow] = bv.y;
        Bs[lk + 2][lrow] = bv.z; Bs[lk + 3][lrow] = bv.w;
        __syncthreads();
#pragma unroll
        for (int kk = 0; kk < 8; kk++) {
            float a[8], b[8];
            *(float4*)(a)     = *(const float4*)(&As[kk][ty * 4]);
            *(float4*)(a + 4) = *(const float4*)(&As[kk][64 + ty * 4]);
            *(float4*)(b)     = *(const float4*)(&Bs[kk][tx * 4]);
            *(float4*)(b + 4) = *(const float4*)(&Bs[kk][64 + tx * 4]);
#pragma unroll
            for (int i = 0; i < 8; i++)
#pragma unroll
                for (int j = 0; j < 8; j++)
                    acc[i][j] = fmaf(a[i], b[j], acc[i][j]);
        }
    }

    const float scale = (mode == 0) ? 0.125f : 1.0f;  // hd^-0.5
#pragma unroll
    for (int i = 0; i < 8; i++) {
        int r = row0 + ty * 4 + (i & 3) + ((i >> 2) << 6);
        int l = r >> 3, nn = r & 7;   // X is [L,N,E] row-major
#pragma unroll
        for (int jg = 0; jg < 2; jg++) {
            int e0 = col0 + tx * 4 + jg * 64;
            float4 bb = *(const float4*)(Bm + e0);
            float v0 = (acc[i][jg * 4 + 0] + bb.x) * scale;
            float v1 = (acc[i][jg * 4 + 1] + bb.y) * scale;
            float v2 = (acc[i][jg * 4 + 2] + bb.z) * scale;
            float v3 = (acc[i][jg * 4 + 3] + bb.w) * scale;
            float o0 = v0, o1 = v1, o2 = v2, o3 = v3;
            if (mode < 2) {
                // rot[n][l][e][{cos,sin}]; interleaved rotate-half
                const float* rp = rot + ((size_t)(nn * LL + l) * EDIM + e0) * 2;
                float4 r01 = *(const float4*)(rp);      // c0 s0 c1 s1
                float4 r23 = *(const float4*)(rp + 4);  // c2 s2 c3 s3
                o0 = v0 * r01.x - v1 * r01.y;
                o1 = v1 * r01.z + v0 * r01.w;
                o2 = v2 * r23.x - v3 * r23.y;
                o3 = v3 * r23.z + v2 * r23.w;
            }
            *(float4*)(dst + (size_t)((nn * NHEAD + (e0 >> 6)) * LL + l) * HDIM
                       + (e0 & 63)) = make_float4(o0, o1, o2, o3);
        }
    }
}

// ============================================================================
// K2: g_sc[nh][l][s] = exp( q[nh][l][:] . k[nh][s][:] ).  128x128 tile, K=64.
// exp fused into the GEMM epilogue. Safe without max-sub: |score| <~ 15 << 88.
// ============================================================================
__global__ __launch_bounds__(256) void scores_kernel()
{
    const int nh = blockIdx.z;
    const int l0 = blockIdx.y * 128;
    const int s0 = blockIdx.x * 128;
    const float* A = g_q + (size_t)nh * LL * HDIM;
    const float* B = g_k + (size_t)nh * SSQ * HDIM;
    float* C = g_sc + ((size_t)nh << 20);

    __shared__ float As[16][132];
    __shared__ float Bs[16][132];

    const int t = threadIdx.x;
    const int lrow = t >> 1;
    const int lk = (t & 1) * 8;
    const int ty = t >> 4, tx = t & 15;

    float acc[8][8] = {};

    for (int k0 = 0; k0 < 64; k0 += 16) {
        float4 a0 = *(const float4*)(A + (size_t)(l0 + lrow) * 64 + k0 + lk);
        float4 a1 = *(const float4*)(A + (size_t)(l0 + lrow) * 64 + k0 + lk + 4);
        float4 b0 = *(const float4*)(B + (size_t)(s0 + lrow) * 64 + k0 + lk);
        float4 b1 = *(const float4*)(B + (size_t)(s0 + lrow) * 64 + k0 + lk + 4);
        __syncthreads();
        As[lk + 0][lrow] = a0.x; As[lk + 1][lrow] = a0.y;
        As[lk + 2][lrow] = a0.z; As[lk + 3][lrow] = a0.w;
        As[lk + 4][lrow] = a1.x; As[lk + 5][lrow] = a1.y;
        As[lk + 6][lrow] = a1.z; As[lk + 7][lrow] = a1.w;
        Bs[lk + 0][lrow] = b0.x; Bs[lk + 1][lrow] = b0.y;
        Bs[lk + 2][lrow] = b0.z; Bs[lk + 3][lrow] = b0.w;
        Bs[lk + 4][lrow] = b1.x; Bs[lk + 5][lrow] = b1.y;
        Bs[lk + 6][lrow] = b1.z; Bs[lk + 7][lrow] = b1.w;
        __syncthreads();
#pragma unroll
        for (int kk = 0; kk < 16; kk++) {
            float a[8], b[8];
            *(float4*)(a)     = *(const float4*)(&As[kk][ty * 4]);
            *(float4*)(a + 4) = *(const float4*)(&As[kk][64 + ty * 4]);
            *(float4*)(b)     = *(const float4*)(&Bs[kk][tx * 4]);
            *(float4*)(b + 4) = *(const float4*)(&Bs[kk][64 + tx * 4]);
#pragma unroll
            for (int i = 0; i < 8; i++)
#pragma unroll
                for (int j = 0; j < 8; j++)
                    acc[i][j] = fmaf(a[i], b[j], acc[i][j]);
        }
    }

#pragma unroll
    for (int i = 0; i < 8; i++) {
        int l = l0 + ty * 4 + (i & 3) + ((i >> 2) << 6);
#pragma unroll
        for (int jg = 0; jg < 2; jg++) {
            int s = s0 + tx * 4 + jg * 64;
            *(float4*)(C + (size_t)l * SSQ + s) = make_float4(
                __expf(acc[i][jg * 4 + 0]), __expf(acc[i][jg * 4 + 1]),
                __expf(acc[i][jg * 4 + 2]), __expf(acc[i][jg * 4 + 3]));
        }
    }
}

// ============================================================================
// K3: column sums over l (queries) of exp'd scores — pure memory pass.
// ============================================================================
__global__ __launch_bounds__(256) void colsum_kernel()
{
    const int nh = blockIdx.y;
    const int s = blockIdx.x * 256 + threadIdx.x;
    const float* sc = g_sc + ((size_t)nh << 20) + s;
    float sum = 0.f;
    for (int l = 0; l < LL; l += 8) {
        float x[8];
#pragma unroll
        for (int j = 0; j < 8; j++) x[j] = sc[(size_t)(l + j) * SSQ];
#pragma unroll
        for (int j = 0; j < 8; j++) sum += x[j];
    }
    g_csum[nh * SSQ + s] = sum;
}

// ============================================================================
// K4: main attention. Per (nh, 128-l tile): stream s in 32-chunks,
// w = p/csum_s + 1e-8, rowsum += w, acc += w @ V, normalize by rowsum.
// ============================================================================
__global__ __launch_bounds__(256) void attn_main_kernel()
{
    const int nh = blockIdx.y;
    const int l0 = blockIdx.x * 128;
    const float* sc = g_sc + ((size_t)nh << 20);
    const float* V = g_v + (size_t)nh * SSQ * HDIM;

    __shared__ float ws[32][136];   // [s_local][l_local]
    __shared__ float vs[32][68];    // [s_local][d]
    __shared__ float rowsum[128];

    const int t = threadIdx.x;
    const int warp = t >> 5, lane = t & 31;
    const int ty = t >> 4, tx = t & 15;
    const int vrow = t >> 3, vq = (t & 7) * 8;

    if (t < 128) rowsum[t] = 0.f;

    float acc[8][4] = {};

    for (int s0 = 0; s0 < SSQ; s0 += 32) {
        float ci = 1.f / g_csum[nh * SSQ + s0 + lane];
        float4 v0 = *(const float4*)(V + (size_t)(s0 + vrow) * 64 + vq);
        float4 v1 = *(const float4*)(V + (size_t)(s0 + vrow) * 64 + vq + 4);
        float xv[16];
#pragma unroll
        for (int i = 0; i < 16; i++)
            xv[i] = sc[(size_t)(l0 + warp + 8 * i) * SSQ + s0 + lane];
        __syncthreads();
        *(float4*)(&vs[vrow][vq]) = v0;
        *(float4*)(&vs[vrow][vq + 4]) = v1;
#pragma unroll
        for (int i = 0; i < 16; i++) {
            float w = xv[i] * ci + 1e-8f;
            ws[lane][warp + 8 * i] = w;
            float rs = warp_sum32(w);
            if (lane == 0) rowsum[warp + 8 * i] += rs;
        }
        __syncthreads();
#pragma unroll
        for (int kk = 0; kk < 32; kk++) {
            float a[8], b[4];
            *(float4*)(a)     = *(const float4*)(&ws[kk][ty * 8]);
            *(float4*)(a + 4) = *(const float4*)(&ws[kk][ty * 8 + 4]);
            *(float4*)(b)     = *(const float4*)(&vs[kk][tx * 4]);
#pragma unroll
            for (int i = 0; i < 8; i++)
#pragma unroll
                for (int j = 0; j < 4; j++)
                    acc[i][j] = fmaf(a[i], b[j], acc[i][j]);
        }
    }
    __syncthreads();
    float* dst = g_attn + (size_t)nh * LL * HDIM;
#pragma unroll
    for (int i = 0; i < 8; i++) {
        int r = ty * 8 + i;
        float inv = 1.f / rowsum[r];
        *(float4*)(dst + (size_t)(l0 + r) * 64 + tx * 4) =
            make_float4(acc[i][0] * inv, acc[i][1] * inv,
                        acc[i][2] * inv, acc[i][3] * inv);
    }
}

// ============================================================================
// K5: memory branch + gate combine. Per (nh, 64-l tile): stream m in 32-chunks:
// sm = q@km^T, p = masked exp (no max needed, |sm|<~9), om = p@vm / rowsum,
// out = gate*om + (1-gate)*attn_main, written to g_ctx[l*8+n][e].
// ============================================================================
__global__ __launch_bounds__(256) void attn_mem_kernel(
    const float* __restrict__ kmem, const float* __restrict__ vmem,
    const float* __restrict__ gatew)
{
    const int nh = blockIdx.y;
    const int n = nh >> 3, h = nh & 7;
    const int l0 = blockIdx.x * 64;

    __shared__ float qs[64][68];
    __shared__ float kc[32][68];
    __shared__ float vc[32][68];
    __shared__ float ps[64][34];
    __shared__ float mask_s[256];

    const int t = threadIdx.x;
    const int ty = t >> 4, tx = t & 15;

    {   // q tile [64][64]
        int row = t >> 2;
        int dq = (t & 3) * 16;
        const float* qp = g_q + ((size_t)nh * LL + l0 + row) * HDIM + dq;
#pragma unroll
        for (int j = 0; j < 4; j++)
            *(float4*)(&qs[row][dq + j * 4]) = *(const float4*)(qp + j * 4);
    }
    mask_s[t] = g_mask[n * MMEM + t] ? 1.f : 0.f;
    __syncthreads();

    float acc2[4][4] = {};
    float rsum[4] = {0.f, 0.f, 0.f, 0.f};

    const int mrow = t >> 3, mq = (t & 7) * 8;

    for (int m0 = 0; m0 < MMEM; m0 += 32) {
        const float* kp = kmem + ((size_t)(m0 + mrow) * NBATCH + n) * EDIM + h * 64 + mq;
        const float* vp = vmem + ((size_t)(m0 + mrow) * NBATCH + n) * EDIM + h * 64 + mq;
        float4 kv0 = *(const float4*)(kp);
        float4 kv1 = *(const float4*)(kp + 4);
        float4 vv0 = *(const float4*)(vp);
        float4 vv1 = *(const float4*)(vp + 4);
        __syncthreads();   // previous GEMM2 done with vc/ps
        *(float4*)(&kc[mrow][mq])     = kv0;
        *(float4*)(&kc[mrow][mq + 4]) = kv1;
        *(float4*)(&vc[mrow][mq])     = vv0;
        *(float4*)(&vc[mrow][mq + 4]) = vv1;
        __syncthreads();

        // GEMM1: sm[64 l][32 m] chunk; thread = 4l x 2m
        float a1[4][2] = {};
#pragma unroll
        for (int kk = 0; kk < 64; kk += 4) {
            float4 b0 = *(const float4*)(&kc[tx * 2][kk]);
            float4 b1 = *(const float4*)(&kc[tx * 2 + 1][kk]);
#pragma unroll
            for (int i = 0; i < 4; i++) {
                float4 a = *(const float4*)(&qs[ty * 4 + i][kk]);
                a1[i][0] = fmaf(a.x, b0.x, fmaf(a.y, b0.y,
                           fmaf(a.z, b0.z, fmaf(a.w, b0.w, a1[i][0]))));
                a1[i][1] = fmaf(a.x, b1.x, fmaf(a.y, b1.y,
                           fmaf(a.z, b1.z, fmaf(a.w, b1.w, a1[i][1]))));
            }
        }
        float msk0 = mask_s[m0 + tx * 2];
        float msk1 = mask_s[m0 + tx * 2 + 1];
#pragma unroll
        for (int i = 0; i < 4; i++) {
            float p0 = (msk0 != 0.f) ? 0.f : __expf(a1[i][0]);
            float p1 = (msk1 != 0.f) ? 0.f : __expf(a1[i][1]);
            ps[ty * 4 + i][tx * 2]     = p0;
            ps[ty * 4 + i][tx * 2 + 1] = p1;
            rsum[i] += p0 + p1;
        }
        __syncthreads();

        // GEMM2: acc2[4 l][4 d] += ps @ vc
#pragma unroll
        for (int kk = 0; kk < 32; kk++) {
            float4 b = *(const float4*)(&vc[kk][tx * 4]);
#pragma unroll
            for (int i = 0; i < 4; i++) {
                float a = ps[ty * 4 + i][kk];
                acc2[i][0] = fmaf(a, b.x, acc2[i][0]);
                acc2[i][1] = fmaf(a, b.y, acc2[i][1]);
                acc2[i][2] = fmaf(a, b.z, acc2[i][2]);
                acc2[i][3] = fmaf(a, b.w, acc2[i][3]);
            }
        }
    }

    // reduce rsum across the 16 tx lanes (each half-warp shares a ty)
#pragma unroll
    for (int i = 0; i < 4; i++) {
        float r = rsum[i];
        r += __shfl_xor_sync(0xffffffffu, r, 8);
        r += __shfl_xor_sync(0xffffffffu, r, 4);
        r += __shfl_xor_sync(0xffffffffu, r, 2);
        r += __shfl_xor_sync(0xffffffffu, r, 1);
        rsum[i] = r;
    }

    const float gate = 1.f / (1.f + __expf(-gatew[h]));
    const float omg = 1.f - gate;
#pragma unroll
    for (int i = 0; i < 4; i++) {
        int l = l0 + ty * 4 + i;
        float inv = 1.f / rsum[i];
        float4 am = *(const float4*)(g_attn + ((size_t)nh * LL + l) * 64 + tx * 4);
        float4 o;
        o.x = gate * (acc2[i][0] * inv) + omg * am.x;
        o.y = gate * (acc2[i][1] * inv) + omg * am.y;
        o.z = gate * (acc2[i][2] * inv) + omg * am.z;
        o.w = gate * (acc2[i][3] * inv) + omg * am.w;
        *(float4*)(g_ctx + ((size_t)l * NBATCH + n) * EDIM + h * 64 + tx * 4) = o;
    }
}

// ============================================================================
// K6: output projection out[r][e] = ctx[r][:] . Wout[e][:] + bias[e].
// ============================================================================
__global__ __launch_bounds__(256) void outproj_kernel(
    const float* __restrict__ W, const float* __restrict__ Bv,
    float* __restrict__ out)
{
    __shared__ float As[8][132];
    __shared__ float Bs[8][132];

    const int t = threadIdx.x;
    const int row0 = blockIdx.y * 128;
    const int col0 = blockIdx.x * 128;
    const int lrow = t >> 1;
    const int lk = (t & 1) * 4;
    const int ty = t >> 4, tx = t & 15;

    float acc[8][8] = {};

    const float* Ap = g_ctx + (size_t)(row0 + lrow) * EDIM + lk;
    const float* Bp = W + (size_t)(col0 + lrow) * EDIM + lk;

    for (int k0 = 0; k0 < EDIM; k0 += 8) {
        float4 av = *(const float4*)(Ap + k0);
        float4 bv = *(const float4*)(Bp + k0);
        __syncthreads();
        As[lk + 0][lrow] = av.x; As[lk + 1][lrow] = av.y;
        As[lk + 2][lrow] = av.z; As[lk + 3][lrow] = av.w;
        Bs[lk + 0][lrow] = bv.x; Bs[lk + 1][lrow] = bv.y;
        Bs[lk + 2][lrow] = bv.z; Bs[lk + 3][lrow] = bv.w;
        __syncthreads();
#pragma unroll
        for (int kk = 0; kk < 8; kk++) {
            float a[8], b[8];
            *(float4*)(a)     = *(const float4*)(&As[kk][ty * 4]);
            *(float4*)(a + 4) = *(const float4*)(&As[kk][64 + ty * 4]);
            *(float4*)(b)     = *(const float4*)(&Bs[kk][tx * 4]);
            *(float4*)(b + 4) = *(const float4*)(&Bs[kk][64 + tx * 4]);
#pragma unroll
            for (int i = 0; i < 8; i++)
#pragma unroll
                for (int j = 0; j < 8; j++)
                    acc[i][j] = fmaf(a[i], b[j], acc[i][j]);
        }
    }

#pragma unroll
    for (int i = 0; i < 8; i++) {
        int r = row0 + ty * 4 + (i & 3) + ((i >> 2) << 6);
#pragma unroll
        for (int jg = 0; jg < 2; jg++) {
            int e0 = col0 + tx * 4 + jg * 64;
            float4 bb = *(const float4*)(Bv + e0);
            *(float4*)(out + (size_t)r * EDIM + e0) = make_float4(
                acc[i][jg * 4 + 0] + bb.x, acc[i][jg * 4 + 1] + bb.y,
                acc[i][jg * 4 + 2] + bb.z, acc[i][jg * 4 + 3] + bb.w);
        }
    }
}

// ============================================================================
extern "C" void kernel_launch(void* const* d_in, const int* in_sizes, int n_in,
                              void* d_out, int out_size)
{
    const float* query = (const float*)d_in[0];
    const float* key   = (const float*)d_in[1];
    const float* value = (const float*)d_in[2];
    const float* Wi    = (const float*)d_in[3];
    const float* Bi    = (const float*)d_in[4];
    const float* Wo    = (const float*)d_in[5];
    const float* Bo    = (const float*)d_in[6];
    const float* rq    = (const float*)d_in[7];
    const float* rk    = (const float*)d_in[8];
    const float* kmem  = (const float*)d_in[9];
    const float* vmem  = (const float*)d_in[10];
    const float* gate  = (const float*)d_in[11];
    const unsigned int* mmask_raw = (const unsigned int*)d_in[12];
    float* out = (float*)d_out;

    mask_decode_kernel<<<1, 256>>>(mmask_raw);
    qkv_kernel<<<dim3(4, 64, 3), 256>>>(query, key, value, Wi, Bi, rq, rk);
    scores_kernel<<<dim3(8, 8, 64), 256>>>();
    colsum_kernel<<<dim3(4, 64), 256>>>();
    attn_main_kernel<<<dim3(8, 64), 256>>>();
    attn_mem_kernel<<<dim3(16, 64), 256>>>(kmem, vmem, gate);
    outproj_kernel<<<dim3(4, 64), 256>>>(Wo, Bo, out);
}

// round 11
// speedup vs baseline: 1.2274x; 1.2274x over previous
#include <cuda_runtime.h>
#include <cuda_bf16.h>

#define LL     1024
#define SSQ    1024
#define MMEM   256
#define NBATCH 8
#define EDIM   512
#define NHEAD  8
#define HDIM   64
#define NH     64
#define RTOT   8192

static __device__ float g_q[NH * LL * HDIM];
static __device__ float g_k[NH * SSQ * HDIM];
static __device__ float g_v[NH * SSQ * HDIM];
static __device__ float g_sc[(size_t)NH * LL * SSQ];
static __device__ float g_cpart[NH * 8 * SSQ];
static __device__ float g_csum[NH * SSQ];
static __device__ float g_attn[NH * LL * HDIM];
static __device__ float g_ctx[(size_t)RTOT * EDIM];
static __device__ unsigned char g_mask[NBATCH * MMEM];

__device__ __forceinline__ float warp_sum32(float x) {
    x += __shfl_xor_sync(0xffffffffu, x, 16);
    x += __shfl_xor_sync(0xffffffffu, x, 8);
    x += __shfl_xor_sync(0xffffffffu, x, 4);
    x += __shfl_xor_sync(0xffffffffu, x, 2);
    x += __shfl_xor_sync(0xffffffffu, x, 1);
    return x;
}

__device__ __forceinline__ void mma_bf16(float* d, const unsigned* a,
                                         unsigned b0, unsigned b1) {
    asm volatile(
        "mma.sync.aligned.m16n8k16.row.col.f32.bf16.bf16.f32 "
        "{%0,%1,%2,%3},{%4,%5,%6,%7},{%8,%9},{%0,%1,%2,%3};\n"
        : "+f"(d[0]), "+f"(d[1]), "+f"(d[2]), "+f"(d[3])
        : "r"(a[0]), "r"(a[1]), "r"(a[2]), "r"(a[3]), "r"(b0), "r"(b1));
}

// pack 2 floats into bf16x2 hi + residual lo (lo half = x, hi half = y)
__device__ __forceinline__ void split2(float x, float y,
                                       unsigned &hi, unsigned &lo) {
    unsigned h;
    asm("cvt.rn.bf16x2.f32 %0, %1, %2;" : "=r"(h) : "f"(y), "f"(x));
    __nv_bfloat162 hb = *reinterpret_cast<__nv_bfloat162*>(&h);
    float rx = x - __bfloat162float(hb.x);
    float ry = y - __bfloat162float(hb.y);
    unsigned l;
    asm("cvt.rn.bf16x2.f32 %0, %1, %2;" : "=r"(l) : "f"(ry), "f"(rx));
    hi = h; lo = l;
}

// ============================================================================
// K0: decode mem_mask regardless of upload encoding.
// ============================================================================
__global__ __launch_bounds__(256) void mask_decode_kernel(
    const unsigned int* __restrict__ m)
{
    __shared__ int enc_flags;
    if (threadIdx.x == 0) enc_flags = 0;
    __syncthreads();
    for (int i = threadIdx.x; i < 512; i += 256) {
        unsigned int w = m[i];
        if ((w & 0xFFFFu) == 0x3F80u) atomicOr(&enc_flags, 2);
        else if ((w >> 8) != 0 && w != 0x3F800000u) atomicOr(&enc_flags, 1);
    }
    __syncthreads();
    int f = enc_flags;
    if (f & 2) {
        const unsigned short* mh = (const unsigned short*)m;
        for (int i = threadIdx.x; i < NBATCH * MMEM; i += 256)
            g_mask[i] = mh[i] ? 1 : 0;
    } else if (f & 1) {
        const unsigned char* mb = (const unsigned char*)m;
        for (int i = threadIdx.x; i < NBATCH * MMEM; i += 256)
            g_mask[i] = mb[i] ? 1 : 0;
    } else {
        for (int i = threadIdx.x; i < NBATCH * MMEM; i += 256)
            g_mask[i] = m[i] ? 1 : 0;
    }
}

// ============================================================================
// K1: unified projection GEMM via split-bf16 mma.sync (3 passes).
// mode 0/1/2 = q/k/v (+bias,+scale,+rotary, scatter to [nh][l][d]);
// mode 3 = output projection (A = g_ctx, +bias, direct store).
// Tile 128x128, K-chunks of 32, 256 threads, 8 warps (4x2).
// ============================================================================
__global__ __launch_bounds__(256, 1) void proj_mma(
    const float* __restrict__ Xq, const float* __restrict__ Xk,
    const float* __restrict__ Xv, const float* __restrict__ Wi,
    const float* __restrict__ Bi, const float* __restrict__ Wo,
    const float* __restrict__ Bo, const float* __restrict__ rq,
    const float* __restrict__ rk, float* __restrict__ out, int base_mode)
{
    const int mode = base_mode + blockIdx.z;
    const float* X  = (mode == 0) ? Xq : (mode == 1) ? Xk :
                      (mode == 2) ? Xv : g_ctx;
    const float* Wm = (mode < 3) ? Wi + (size_t)mode * EDIM * EDIM : Wo;
    const float* Bm = (mode < 3) ? Bi + mode * EDIM : Bo;
    const float* rot = (mode == 0) ? rq : rk;

    __shared__ unsigned Ah[128][18], Al[128][18], Bh[128][18], Bl[128][18];

    const int t = threadIdx.x;
    const int warp = t >> 5, lane = t & 31;
    const int g = lane >> 2, tq = lane & 3;
    const int wm = warp >> 1, wn = warp & 1;
    const int row0 = blockIdx.y * 128, col0 = blockIdx.x * 128;

    float D[2][8][4] = {};
    float4 ra[4], rb[4];

#pragma unroll
    for (int j = 0; j < 4; j++) {
        int idx = t + 256 * j, r = idx >> 3, q4 = idx & 7;
        ra[j] = *(const float4*)(X  + (size_t)(row0 + r) * EDIM + q4 * 4);
        rb[j] = *(const float4*)(Wm + (size_t)(col0 + r) * EDIM + q4 * 4);
    }

    for (int kc = 0; kc < 16; kc++) {
        __syncthreads();
#pragma unroll
        for (int j = 0; j < 4; j++) {
            int idx = t + 256 * j, r = idx >> 3, q4 = idx & 7;
            unsigned h0, l0v, h1, l1v;
            split2(ra[j].x, ra[j].y, h0, l0v);
            split2(ra[j].z, ra[j].w, h1, l1v);
            *(uint2*)&Ah[r][q4 * 2] = make_uint2(h0, h1);
            *(uint2*)&Al[r][q4 * 2] = make_uint2(l0v, l1v);
            split2(rb[j].x, rb[j].y, h0, l0v);
            split2(rb[j].z, rb[j].w, h1, l1v);
            *(uint2*)&Bh[r][q4 * 2] = make_uint2(h0, h1);
            *(uint2*)&Bl[r][q4 * 2] = make_uint2(l0v, l1v);
        }
        __syncthreads();
        if (kc < 15) {
#pragma unroll
            for (int j = 0; j < 4; j++) {
                int idx = t + 256 * j, r = idx >> 3, q4 = idx & 7;
                ra[j] = *(const float4*)(X  + (size_t)(row0 + r) * EDIM +
                                         (kc + 1) * 32 + q4 * 4);
                rb[j] = *(const float4*)(Wm + (size_t)(col0 + r) * EDIM +
                                         (kc + 1) * 32 + q4 * 4);
            }
        }
#pragma unroll
        for (int ks = 0; ks < 2; ks++) {
            unsigned ah[2][4], al_[2][4];
#pragma unroll
            for (int mt = 0; mt < 2; mt++) {
                int m = wm * 32 + mt * 16 + g;
                ah[mt][0]  = Ah[m][ks * 8 + tq];
                ah[mt][1]  = Ah[m + 8][ks * 8 + tq];
                ah[mt][2]  = Ah[m][ks * 8 + tq + 4];
                ah[mt][3]  = Ah[m + 8][ks * 8 + tq + 4];
                al_[mt][0] = Al[m][ks * 8 + tq];
                al_[mt][1] = Al[m + 8][ks * 8 + tq];
                al_[mt][2] = Al[m][ks * 8 + tq + 4];
                al_[mt][3] = Al[m + 8][ks * 8 + tq + 4];
            }
#pragma unroll
            for (int nt = 0; nt < 8; nt++) {
                int n = wn * 64 + nt * 8 + g;
                unsigned bh0 = Bh[n][ks * 8 + tq], bh1 = Bh[n][ks * 8 + tq + 4];
                unsigned bl0 = Bl[n][ks * 8 + tq], bl1 = Bl[n][ks * 8 + tq + 4];
#pragma unroll
                for (int mt = 0; mt < 2; mt++) {
                    mma_bf16(D[mt][nt], ah[mt], bh0, bh1);
                    mma_bf16(D[mt][nt], ah[mt], bl0, bl1);
                    mma_bf16(D[mt][nt], al_[mt], bh0, bh1);
                }
            }
        }
    }

    const float scale = (mode == 0) ? 0.125f : 1.0f;
    float* dst = (mode == 0) ? g_q : (mode == 1) ? g_k : g_v;
#pragma unroll
    for (int mt = 0; mt < 2; mt++) {
#pragma unroll
        for (int half = 0; half < 2; half++) {
            int r = row0 + wm * 32 + mt * 16 + g + half * 8;
#pragma unroll
            for (int nt = 0; nt < 8; nt++) {
                int c = col0 + wn * 64 + nt * 8 + tq * 2;
                float v0 = D[mt][nt][half * 2 + 0] + Bm[c];
                float v1 = D[mt][nt][half * 2 + 1] + Bm[c + 1];
                if (mode == 3) {
                    *(float2*)(out + (size_t)r * EDIM + c) = make_float2(v0, v1);
                } else {
                    v0 *= scale; v1 *= scale;
                    int l = r >> 3, nn = r & 7;
                    float o0 = v0, o1 = v1;
                    if (mode < 2) {
                        const float* rp = rot +
                            ((size_t)(nn * LL + l) * EDIM + c) * 2;
                        float4 rr = *(const float4*)rp;   // c0 s0 c1 s1
                        o0 = v0 * rr.x - v1 * rr.y;
                        o1 = v1 * rr.z + v0 * rr.w;
                    }
                    *(float2*)(dst + (size_t)((nn * NHEAD + (c >> 6)) * LL + l)
                               * HDIM + (c & 63)) = make_float2(o0, o1);
                }
            }
        }
    }
}

// ============================================================================
// K2: exp(scores) GEMM (fp32) + fused per-block column partial sums.
// ============================================================================
__global__ __launch_bounds__(256) void scores_kernel()
{
    const int nh = blockIdx.z;
    const int l0 = blockIdx.y * 128;
    const int s0 = blockIdx.x * 128;
    const float* A = g_q + (size_t)nh * LL * HDIM;
    const float* B = g_k + (size_t)nh * SSQ * HDIM;
    float* C = g_sc + ((size_t)nh << 20);

    __shared__ float As[16][132];
    __shared__ float Bs[16][132];
    __shared__ float red[16][128];

    const int t = threadIdx.x;
    const int lrow = t >> 1;
    const int lk = (t & 1) * 8;
    const int ty = t >> 4, tx = t & 15;

    float acc[8][8] = {};

    for (int k0 = 0; k0 < 64; k0 += 16) {
        float4 a0 = *(const float4*)(A + (size_t)(l0 + lrow) * 64 + k0 + lk);
        float4 a1 = *(const float4*)(A + (size_t)(l0 + lrow) * 64 + k0 + lk + 4);
        float4 b0 = *(const float4*)(B + (size_t)(s0 + lrow) * 64 + k0 + lk);
        float4 b1 = *(const float4*)(B + (size_t)(s0 + lrow) * 64 + k0 + lk + 4);
        __syncthreads();
        As[lk + 0][lrow] = a0.x; As[lk + 1][lrow] = a0.y;
        As[lk + 2][lrow] = a0.z; As[lk + 3][lrow] = a0.w;
        As[lk + 4][lrow] = a1.x; As[lk + 5][lrow] = a1.y;
        As[lk + 6][lrow] = a1.z; As[lk + 7][lrow] = a1.w;
        Bs[lk + 0][lrow] = b0.x; Bs[lk + 1][lrow] = b0.y;
        Bs[lk + 2][lrow] = b0.z; Bs[lk + 3][lrow] = b0.w;
        Bs[lk + 4][lrow] = b1.x; Bs[lk + 5][lrow] = b1.y;
        Bs[lk + 6][lrow] = b1.z; Bs[lk + 7][lrow] = b1.w;
        __syncthreads();
#pragma unroll
        for (int kk = 0; kk < 16; kk++) {
            float a[8], b[8];
            *(float4*)(a)     = *(const float4*)(&As[kk][ty * 4]);
            *(float4*)(a + 4) = *(const float4*)(&As[kk][64 + ty * 4]);
            *(float4*)(b)     = *(const float4*)(&Bs[kk][tx * 4]);
            *(float4*)(b + 4) = *(const float4*)(&Bs[kk][64 + tx * 4]);
#pragma unroll
            for (int i = 0; i < 8; i++)
#pragma unroll
                for (int j = 0; j < 8; j++)
                    acc[i][j] = fmaf(a[i], b[j], acc[i][j]);
        }
    }

    float cs[8] = {};
#pragma unroll
    for (int i = 0; i < 8; i++) {
        int l = l0 + ty * 4 + (i & 3) + ((i >> 2) << 6);
#pragma unroll
        for (int jg = 0; jg < 2; jg++) {
            int s = s0 + tx * 4 + jg * 64;
            float e0 = __expf(acc[i][jg * 4 + 0]);
            float e1 = __expf(acc[i][jg * 4 + 1]);
            float e2 = __expf(acc[i][jg * 4 + 2]);
            float e3 = __expf(acc[i][jg * 4 + 3]);
            *(float4*)(C + (size_t)l * SSQ + s) = make_float4(e0, e1, e2, e3);
            cs[jg * 4 + 0] += e0; cs[jg * 4 + 1] += e1;
            cs[jg * 4 + 2] += e2; cs[jg * 4 + 3] += e3;
        }
    }
    __syncthreads();   // As/Bs reuse done; red write after all acc reads done
#pragma unroll
    for (int jg = 0; jg < 2; jg++)
#pragma unroll
        for (int q = 0; q < 4; q++)
            red[ty][tx * 4 + jg * 64 + q] = cs[jg * 4 + q];
    __syncthreads();
    if (t < 128) {
        float tot = 0.f;
#pragma unroll
        for (int j = 0; j < 16; j++) tot += red[j][t];
        g_cpart[((size_t)nh * 8 + blockIdx.y) * SSQ + s0 + t] = tot;
    }
}

// ============================================================================
// K3: reduce 8 column partials -> g_csum (deterministic).
// ============================================================================
__global__ __launch_bounds__(256) void colsum2_kernel()
{
    int nh = blockIdx.y, s = blockIdx.x * 256 + threadIdx.x;
    float sum = 0.f;
#pragma unroll
    for (int j = 0; j < 8; j++)
        sum += g_cpart[((size_t)nh * 8 + j) * SSQ + s];
    g_csum[nh * SSQ + s] = sum;
}

// ============================================================================
// K4: main attention (unchanged, known-correct).
// ============================================================================
__global__ __launch_bounds__(256) void attn_main_kernel()
{
    const int nh = blockIdx.y;
    const int l0 = blockIdx.x * 128;
    const float* sc = g_sc + ((size_t)nh << 20);
    const float* V = g_v + (size_t)nh * SSQ * HDIM;

    __shared__ float ws[32][136];
    __shared__ float vs[32][68];
    __shared__ float rowsum[128];

    const int t = threadIdx.x;
    const int warp = t >> 5, lane = t & 31;
    const int ty = t >> 4, tx = t & 15;
    const int vrow = t >> 3, vq = (t & 7) * 8;

    if (t < 128) rowsum[t] = 0.f;

    float acc[8][4] = {};

    for (int s0 = 0; s0 < SSQ; s0 += 32) {
        float ci = 1.f / g_csum[nh * SSQ + s0 + lane];
        float4 v0 = *(const float4*)(V + (size_t)(s0 + vrow) * 64 + vq);
        float4 v1 = *(const float4*)(V + (size_t)(s0 + vrow) * 64 + vq + 4);
        float xv[16];
#pragma unroll
        for (int i = 0; i < 16; i++)
            xv[i] = sc[(size_t)(l0 + warp + 8 * i) * SSQ + s0 + lane];
        __syncthreads();
        *(float4*)(&vs[vrow][vq]) = v0;
        *(float4*)(&vs[vrow][vq + 4]) = v1;
#pragma unroll
        for (int i = 0; i < 16; i++) {
            float w = xv[i] * ci + 1e-8f;
            ws[lane][warp + 8 * i] = w;
            float rs = warp_sum32(w);
            if (lane == 0) rowsum[warp + 8 * i] += rs;
        }
        __syncthreads();
#pragma unroll
        for (int kk = 0; kk < 32; kk++) {
            float a[8], b[4];
            *(float4*)(a)     = *(const float4*)(&ws[kk][ty * 8]);
            *(float4*)(a + 4) = *(const float4*)(&ws[kk][ty * 8 + 4]);
            *(float4*)(b)     = *(const float4*)(&vs[kk][tx * 4]);
#pragma unroll
            for (int i = 0; i < 8; i++)
#pragma unroll
                for (int j = 0; j < 4; j++)
                    acc[i][j] = fmaf(a[i], b[j], acc[i][j]);
        }
    }
    __syncthreads();
    float* dst = g_attn + (size_t)nh * LL * HDIM;
#pragma unroll
    for (int i = 0; i < 8; i++) {
        int r = ty * 8 + i;
        float inv = 1.f / rowsum[r];
        *(float4*)(dst + (size_t)(l0 + r) * 64 + tx * 4) =
            make_float4(acc[i][0] * inv, acc[i][1] * inv,
                        acc[i][2] * inv, acc[i][3] * inv);
    }
}

// ============================================================================
// K5: memory branch + gate combine (unchanged, known-correct).
// ============================================================================
__global__ __launch_bounds__(256) void attn_mem_kernel(
    const float* __restrict__ kmem, const float* __restrict__ vmem,
    const float* __restrict__ gatew)
{
    const int nh = blockIdx.y;
    const int n = nh >> 3, h = nh & 7;
    const int l0 = blockIdx.x * 64;

    __shared__ float qs[64][68];
    __shared__ float kc[32][68];
    __shared__ float vc[32][68];
    __shared__ float ps[64][34];
    __shared__ float mask_s[256];

    const int t = threadIdx.x;
    const int ty = t >> 4, tx = t & 15;

    {
        int row = t >> 2;
        int dq = (t & 3) * 16;
        const float* qp = g_q + ((size_t)nh * LL + l0 + row) * HDIM + dq;
#pragma unroll
        for (int j = 0; j < 4; j++)
            *(float4*)(&qs[row][dq + j * 4]) = *(const float4*)(qp + j * 4);
    }
    mask_s[t] = g_mask[n * MMEM + t] ? 1.f : 0.f;
    __syncthreads();

    float acc2[4][4] = {};
    float rsum[4] = {0.f, 0.f, 0.f, 0.f};

    const int mrow = t >> 3, mq = (t & 7) * 8;

    for (int m0 = 0; m0 < MMEM; m0 += 32) {
        const float* kp = kmem + ((size_t)(m0 + mrow) * NBATCH + n) * EDIM + h * 64 + mq;
        const float* vp = vmem + ((size_t)(m0 + mrow) * NBATCH + n) * EDIM + h * 64 + mq;
        float4 kv0 = *(const float4*)(kp);
        float4 kv1 = *(const float4*)(kp + 4);
        float4 vv0 = *(const float4*)(vp);
        float4 vv1 = *(const float4*)(vp + 4);
        __syncthreads();
        *(float4*)(&kc[mrow][mq])     = kv0;
        *(float4*)(&kc[mrow][mq + 4]) = kv1;
        *(float4*)(&vc[mrow][mq])     = vv0;
        *(float4*)(&vc[mrow][mq + 4]) = vv1;
        __syncthreads();

        float a1[4][2] = {};
#pragma unroll
        for (int kk = 0; kk < 64; kk += 4) {
            float4 b0 = *(const float4*)(&kc[tx * 2][kk]);
            float4 b1 = *(const float4*)(&kc[tx * 2 + 1][kk]);
#pragma unroll
            for (int i = 0; i < 4; i++) {
                float4 a = *(const float4*)(&qs[ty * 4 + i][kk]);
                a1[i][0] = fmaf(a.x, b0.x, fmaf(a.y, b0.y,
                           fmaf(a.z, b0.z, fmaf(a.w, b0.w, a1[i][0]))));
                a1[i][1] = fmaf(a.x, b1.x, fmaf(a.y, b1.y,
                           fmaf(a.z, b1.z, fmaf(a.w, b1.w, a1[i][1]))));
            }
        }
        float msk0 = mask_s[m0 + tx * 2];
        float msk1 = mask_s[m0 + tx * 2 + 1];
#pragma unroll
        for (int i = 0; i < 4; i++) {
            float p0 = (msk0 != 0.f) ? 0.f : __expf(a1[i][0]);
            float p1 = (msk1 != 0.f) ? 0.f : __expf(a1[i][1]);
            ps[ty * 4 + i][tx * 2]     = p0;
            ps[ty * 4 + i][tx * 2 + 1] = p1;
            rsum[i] += p0 + p1;
        }
        __syncthreads();

#pragma unroll
        for (int kk = 0; kk < 32; kk++) {
            float4 b = *(const float4*)(&vc[kk][tx * 4]);
#pragma unroll
            for (int i = 0; i < 4; i++) {
                float a = ps[ty * 4 + i][kk];
                acc2[i][0] = fmaf(a, b.x, acc2[i][0]);
                acc2[i][1] = fmaf(a, b.y, acc2[i][1]);
                acc2[i][2] = fmaf(a, b.z, acc2[i][2]);
                acc2[i][3] = fmaf(a, b.w, acc2[i][3]);
            }
        }
    }

#pragma unroll
    for (int i = 0; i < 4; i++) {
        float r = rsum[i];
        r += __shfl_xor_sync(0xffffffffu, r, 8);
        r += __shfl_xor_sync(0xffffffffu, r, 4);
        r += __shfl_xor_sync(0xffffffffu, r, 2);
        r += __shfl_xor_sync(0xffffffffu, r, 1);
        rsum[i] = r;
    }

    const float gate = 1.f / (1.f + __expf(-gatew[h]));
    const float omg = 1.f - gate;
#pragma unroll
    for (int i = 0; i < 4; i++) {
        int l = l0 + ty * 4 + i;
        float inv = 1.f / rsum[i];
        float4 am = *(const float4*)(g_attn + ((size_t)nh * LL + l) * 64 + tx * 4);
        float4 o;
        o.x = gate * (acc2[i][0] * inv) + omg * am.x;
        o.y = gate * (acc2[i][1] * inv) + omg * am.y;
        o.z = gate * (acc2[i][2] * inv) + omg * am.z;
        o.w = gate * (acc2[i][3] * inv) + omg * am.w;
        *(float4*)(g_ctx + ((size_t)l * NBATCH + n) * EDIM + h * 64 + tx * 4) = o;
    }
}

// ============================================================================
extern "C" void kernel_launch(void* const* d_in, const int* in_sizes, int n_in,
                              void* d_out, int out_size)
{
    const float* query = (const float*)d_in[0];
    const float* key   = (const float*)d_in[1];
    const float* value = (const float*)d_in[2];
    const float* Wi    = (const float*)d_in[3];
    const float* Bi    = (const float*)d_in[4];
    const float* Wo    = (const float*)d_in[5];
    const float* Bo    = (const float*)d_in[6];
    const float* rq    = (const float*)d_in[7];
    const float* rk    = (const float*)d_in[8];
    const float* kmem  = (const float*)d_in[9];
    const float* vmem  = (const float*)d_in[10];
    const float* gate  = (const float*)d_in[11];
    const unsigned int* mmask_raw = (const unsigned int*)d_in[12];
    float* out = (float*)d_out;

    mask_decode_kernel<<<1, 256>>>(mmask_raw);
    proj_mma<<<dim3(4, 64, 3), 256>>>(query, key, value, Wi, Bi, Wo, Bo,
                                      rq, rk, out, 0);
    scores_kernel<<<dim3(8, 8, 64), 256>>>();
    colsum2_kernel<<<dim3(4, 64), 256>>>();
    attn_main_kernel<<<dim3(8, 64), 256>>>();
    attn_mem_kernel<<<dim3(16, 64), 256>>>(kmem, vmem, gate);
    proj_mma<<<dim3(4, 64, 1), 256>>>(query, key, value, Wi, Bi, Wo, Bo,
                                      rq, rk, out, 3);
}

// round 13
// speedup vs baseline: 1.3510x; 1.1007x over previous
#include <cuda_runtime.h>
#include <cuda_bf16.h>

#define LL     1024
#define SSQ    1024
#define MMEM   256
#define NBATCH 8
#define EDIM   512
#define NHEAD  8
#define HDIM   64
#define NH     64
#define RTOT   8192

static __device__ float g_q[NH * LL * HDIM];
static __device__ float g_k[NH * SSQ * HDIM];
static __device__ float g_v[NH * SSQ * HDIM];
static __device__ float g_sc[(size_t)NH * LL * SSQ];
static __device__ float g_cpart[NH * 8 * SSQ];
static __device__ float g_csum[NH * SSQ];
static __device__ float g_attn[NH * LL * HDIM];
static __device__ float g_ctx[(size_t)RTOT * EDIM];
static __device__ unsigned char g_mask[NBATCH * MMEM];

__device__ __forceinline__ void mma_bf16(float* d, const unsigned* a,
                                         unsigned b0, unsigned b1) {
    asm volatile(
        "mma.sync.aligned.m16n8k16.row.col.f32.bf16.bf16.f32 "
        "{%0,%1,%2,%3},{%4,%5,%6,%7},{%8,%9},{%0,%1,%2,%3};\n"
        : "+f"(d[0]), "+f"(d[1]), "+f"(d[2]), "+f"(d[3])
        : "r"(a[0]), "r"(a[1]), "r"(a[2]), "r"(a[3]), "r"(b0), "r"(b1));
}

// pack 2 floats into bf16x2 hi + residual lo (x -> low half, y -> high half)
__device__ __forceinline__ void split2(float x, float y,
                                       unsigned &hi, unsigned &lo) {
    unsigned h;
    asm("cvt.rn.bf16x2.f32 %0, %1, %2;" : "=r"(h) : "f"(y), "f"(x));
    __nv_bfloat162 hb = *reinterpret_cast<__nv_bfloat162*>(&h);
    float rx = x - __bfloat162float(hb.x);
    float ry = y - __bfloat162float(hb.y);
    unsigned l;
    asm("cvt.rn.bf16x2.f32 %0, %1, %2;" : "=r"(l) : "f"(ry), "f"(rx));
    hi = h; lo = l;
}

// ============================================================================
// K0: decode mem_mask regardless of upload encoding.
// ============================================================================
__global__ __launch_bounds__(256) void mask_decode_kernel(
    const unsigned int* __restrict__ m)
{
    __shared__ int enc_flags;
    if (threadIdx.x == 0) enc_flags = 0;
    __syncthreads();
    for (int i = threadIdx.x; i < 512; i += 256) {
        unsigned int w = m[i];
        if ((w & 0xFFFFu) == 0x3F80u) atomicOr(&enc_flags, 2);
        else if ((w >> 8) != 0 && w != 0x3F800000u) atomicOr(&enc_flags, 1);
    }
    __syncthreads();
    int f = enc_flags;
    if (f & 2) {
        const unsigned short* mh = (const unsigned short*)m;
        for (int i = threadIdx.x; i < NBATCH * MMEM; i += 256)
            g_mask[i] = mh[i] ? 1 : 0;
    } else if (f & 1) {
        const unsigned char* mb = (const unsigned char*)m;
        for (int i = threadIdx.x; i < NBATCH * MMEM; i += 256)
            g_mask[i] = mb[i] ? 1 : 0;
    } else {
        for (int i = threadIdx.x; i < NBATCH * MMEM; i += 256)
            g_mask[i] = m[i] ? 1 : 0;
    }
}

// ============================================================================
// K1: unified projection GEMM via split-bf16 mma.sync (3 passes). Unchanged.
// ============================================================================
__global__ __launch_bounds__(256, 1) void proj_mma(
    const float* __restrict__ Xq, const float* __restrict__ Xk,
    const float* __restrict__ Xv, const float* __restrict__ Wi,
    const float* __restrict__ Bi, const float* __restrict__ Wo,
    const float* __restrict__ Bo, const float* __restrict__ rq,
    const float* __restrict__ rk, float* __restrict__ out, int base_mode)
{
    const int mode = base_mode + blockIdx.z;
    const float* X  = (mode == 0) ? Xq : (mode == 1) ? Xk :
                      (mode == 2) ? Xv : g_ctx;
    const float* Wm = (mode < 3) ? Wi + (size_t)mode * EDIM * EDIM : Wo;
    const float* Bm = (mode < 3) ? Bi + mode * EDIM : Bo;
    const float* rot = (mode == 0) ? rq : rk;

    __shared__ unsigned Ah[128][18], Al[128][18], Bh[128][18], Bl[128][18];

    const int t = threadIdx.x;
    const int warp = t >> 5, lane = t & 31;
    const int g = lane >> 2, tq = lane & 3;
    const int wm = warp >> 1, wn = warp & 1;
    const int row0 = blockIdx.y * 128, col0 = blockIdx.x * 128;

    float D[2][8][4] = {};
    float4 ra[4], rb[4];

#pragma unroll
    for (int j = 0; j < 4; j++) {
        int idx = t + 256 * j, r = idx >> 3, q4 = idx & 7;
        ra[j] = *(const float4*)(X  + (size_t)(row0 + r) * EDIM + q4 * 4);
        rb[j] = *(const float4*)(Wm + (size_t)(col0 + r) * EDIM + q4 * 4);
    }

    for (int kc = 0; kc < 16; kc++) {
        __syncthreads();
#pragma unroll
        for (int j = 0; j < 4; j++) {
            int idx = t + 256 * j, r = idx >> 3, q4 = idx & 7;
            unsigned h0, l0v, h1, l1v;
            split2(ra[j].x, ra[j].y, h0, l0v);
            split2(ra[j].z, ra[j].w, h1, l1v);
            *(uint2*)&Ah[r][q4 * 2] = make_uint2(h0, h1);
            *(uint2*)&Al[r][q4 * 2] = make_uint2(l0v, l1v);
            split2(rb[j].x, rb[j].y, h0, l0v);
            split2(rb[j].z, rb[j].w, h1, l1v);
            *(uint2*)&Bh[r][q4 * 2] = make_uint2(h0, h1);
            *(uint2*)&Bl[r][q4 * 2] = make_uint2(l0v, l1v);
        }
        __syncthreads();
        if (kc < 15) {
#pragma unroll
            for (int j = 0; j < 4; j++) {
                int idx = t + 256 * j, r = idx >> 3, q4 = idx & 7;
                ra[j] = *(const float4*)(X  + (size_t)(row0 + r) * EDIM +
                                         (kc + 1) * 32 + q4 * 4);
                rb[j] = *(const float4*)(Wm + (size_t)(col0 + r) * EDIM +
                                         (kc + 1) * 32 + q4 * 4);
            }
        }
#pragma unroll
        for (int ks = 0; ks < 2; ks++) {
            unsigned ah[2][4], al_[2][4];
#pragma unroll
            for (int mt = 0; mt < 2; mt++) {
                int m = wm * 32 + mt * 16 + g;
                ah[mt][0]  = Ah[m][ks * 8 + tq];
                ah[mt][1]  = Ah[m + 8][ks * 8 + tq];
                ah[mt][2]  = Ah[m][ks * 8 + tq + 4];
                ah[mt][3]  = Ah[m + 8][ks * 8 + tq + 4];
                al_[mt][0] = Al[m][ks * 8 + tq];
                al_[mt][1] = Al[m + 8][ks * 8 + tq];
                al_[mt][2] = Al[m][ks * 8 + tq + 4];
                al_[mt][3] = Al[m + 8][ks * 8 + tq + 4];
            }
#pragma unroll
            for (int nt = 0; nt < 8; nt++) {
                int n = wn * 64 + nt * 8 + g;
                unsigned bh0 = Bh[n][ks * 8 + tq], bh1 = Bh[n][ks * 8 + tq + 4];
                unsigned bl0 = Bl[n][ks * 8 + tq], bl1 = Bl[n][ks * 8 + tq + 4];
#pragma unroll
                for (int mt = 0; mt < 2; mt++) {
                    mma_bf16(D[mt][nt], ah[mt], bh0, bh1);
                    mma_bf16(D[mt][nt], ah[mt], bl0, bl1);
                    mma_bf16(D[mt][nt], al_[mt], bh0, bh1);
                }
            }
        }
    }

    const float scale = (mode == 0) ? 0.125f : 1.0f;
    float* dst = (mode == 0) ? g_q : (mode == 1) ? g_k : g_v;
#pragma unroll
    for (int mt = 0; mt < 2; mt++) {
#pragma unroll
        for (int half = 0; half < 2; half++) {
            int r = row0 + wm * 32 + mt * 16 + g + half * 8;
#pragma unroll
            for (int nt = 0; nt < 8; nt++) {
                int c = col0 + wn * 64 + nt * 8 + tq * 2;
                float v0 = D[mt][nt][half * 2 + 0] + Bm[c];
                float v1 = D[mt][nt][half * 2 + 1] + Bm[c + 1];
                if (mode == 3) {
                    *(float2*)(out + (size_t)r * EDIM + c) = make_float2(v0, v1);
                } else {
                    v0 *= scale; v1 *= scale;
                    int l = r >> 3, nn = r & 7;
                    float o0 = v0, o1 = v1;
                    if (mode < 2) {
                        const float* rp = rot +
                            ((size_t)(nn * LL + l) * EDIM + c) * 2;
                        float4 rr = *(const float4*)rp;
                        o0 = v0 * rr.x - v1 * rr.y;
                        o1 = v1 * rr.z + v0 * rr.w;
                    }
                    *(float2*)(dst + (size_t)((nn * NHEAD + (c >> 6)) * LL + l)
                               * HDIM + (c & 63)) = make_float2(o0, o1);
                }
            }
        }
    }
}

// ============================================================================
// K2: scores = exp(q.k) via EXACT 4-pass split-bf16 mma (buffer swap) +
// fused per-block column partials. Tile 128l x 128s, K=64.
// Stride 36 words (144B) -> 16B-aligned rows for uint4 stores, conflict-free.
// ============================================================================
__global__ __launch_bounds__(256, 1) void scores_mma()
{
    __shared__ unsigned X[128][36], Y[128][36];
    __shared__ float red[8][64];

    const int nh = blockIdx.z;
    const int l0 = blockIdx.y * 128, s0 = blockIdx.x * 128;
    const int t = threadIdx.x;
    const int warp = t >> 5, lane = t & 31;
    const int g = lane >> 2, tq = lane & 3;
    const int wm = warp >> 1, wn = warp & 1;

    const float* Q = g_q + ((size_t)nh * LL + l0) * HDIM;
    const float* K = g_k + ((size_t)nh * SSQ + s0) * HDIM;

    float D[2][8][4] = {};

    // stage: convert a 128x64 fp32 tile to packed bf16 (hi or lo part)
    auto stage = [&](unsigned (*buf)[36], const float* src, int want_lo) {
#pragma unroll
        for (int j = 0; j < 4; j++) {
            int idx = t + 256 * j, r = idx >> 3, q4 = idx & 7;
            float4 v0 = *(const float4*)(src + (size_t)r * 64 + q4 * 8);
            float4 v1 = *(const float4*)(src + (size_t)r * 64 + q4 * 8 + 4);
            unsigned h0, lo0, h1, lo1, h2, lo2, h3, lo3;
            split2(v0.x, v0.y, h0, lo0);
            split2(v0.z, v0.w, h1, lo1);
            split2(v1.x, v1.y, h2, lo2);
            split2(v1.z, v1.w, h3, lo3);
            if (want_lo) { h0 = lo0; h1 = lo1; h2 = lo2; h3 = lo3; }
            *(uint4*)&buf[r][q4 * 4] = make_uint4(h0, h1, h2, h3);
        }
    };
    auto do_pass = [&]() {
#pragma unroll
        for (int ks = 0; ks < 4; ks++) {
            unsigned a[2][4];
#pragma unroll
            for (int mt = 0; mt < 2; mt++) {
                int m = wm * 32 + mt * 16 + g;
                a[mt][0] = X[m][ks * 8 + tq];
                a[mt][1] = X[m + 8][ks * 8 + tq];
                a[mt][2] = X[m][ks * 8 + tq + 4];
                a[mt][3] = X[m + 8][ks * 8 + tq + 4];
            }
#pragma unroll
            for (int nt = 0; nt < 8; nt++) {
                int n = wn * 64 + nt * 8 + g;
                unsigned b0 = Y[n][ks * 8 + tq], b1 = Y[n][ks * 8 + tq + 4];
#pragma unroll
                for (int mt = 0; mt < 2; mt++)
                    mma_bf16(D[mt][nt], a[mt], b0, b1);
            }
        }
    };

    stage(X, Q, 0); stage(Y, K, 0);
    __syncthreads(); do_pass();          // qh*kh
    __syncthreads(); stage(Y, K, 1);
    __syncthreads(); do_pass();          // qh*kl
    __syncthreads(); stage(X, Q, 1);
    __syncthreads(); do_pass();          // ql*kl
    __syncthreads(); stage(Y, K, 0);
    __syncthreads(); do_pass();          // ql*kh  -> exact

    float* C = g_sc + ((size_t)nh << 20);
    float cs[8][2] = {};
#pragma unroll
    for (int mt = 0; mt < 2; mt++) {
#pragma unroll
        for (int half = 0; half < 2; half++) {
            int l = l0 + wm * 32 + mt * 16 + g + half * 8;
#pragma unroll
            for (int nt = 0; nt < 8; nt++) {
                int s = s0 + wn * 64 + nt * 8 + tq * 2;
                float e0 = __expf(D[mt][nt][half * 2 + 0]);
                float e1 = __expf(D[mt][nt][half * 2 + 1]);
                *(float2*)(C + (size_t)l * SSQ + s) = make_float2(e0, e1);
                cs[nt][0] += e0;
                cs[nt][1] += e1;
            }
        }
    }
    // reduce column sums: over g within warp, then across the 4 wm-warps
#pragma unroll
    for (int nt = 0; nt < 8; nt++) {
#pragma unroll
        for (int c2 = 0; c2 < 2; c2++) {
            float v = cs[nt][c2];
            v += __shfl_xor_sync(0xffffffffu, v, 4);
            v += __shfl_xor_sync(0xffffffffu, v, 8);
            v += __shfl_xor_sync(0xffffffffu, v, 16);
            if (g == 0) red[warp][nt * 8 + tq * 2 + c2] = v;
        }
    }
    __syncthreads();
    if (t < 128) {
        int wnn = t >> 6, cc = t & 63;
        float tot = red[wnn][cc] + red[wnn + 2][cc] +
                    red[wnn + 4][cc] + red[wnn + 6][cc];
        g_cpart[((size_t)nh * 8 + blockIdx.y) * SSQ + s0 + t] = tot;
    }
}

// ============================================================================
// K3: reduce 8 column partials -> g_csum (deterministic).
// ============================================================================
__global__ __launch_bounds__(256) void colsum2_kernel()
{
    int nh = blockIdx.y, s = blockIdx.x * 256 + threadIdx.x;
    float sum = 0.f;
#pragma unroll
    for (int j = 0; j < 8; j++)
        sum += g_cpart[((size_t)nh * 8 + j) * SSQ + s];
    g_csum[nh * SSQ + s] = sum;
}

// ============================================================================
// K4: main attention via 3-pass split-bf16 mma. Tile 128l x 64d; 32 s-chunks.
// ============================================================================
__global__ __launch_bounds__(256, 1) void attn_main_mma()
{
    __shared__ unsigned Wh[128][18], Wl[128][18];
    __shared__ unsigned Vth[64][18], Vtl[64][18];
    __shared__ float cinv[1024];
    __shared__ float rsp[128][4];
    __shared__ float rowinv[128];

    const int nh = blockIdx.y, l0 = blockIdx.x * 128;
    const int t = threadIdx.x;
    const int warp = t >> 5, lane = t & 31;
    const int g = lane >> 2, tq = lane & 3;
    const int wm = warp >> 1, wn = warp & 1;

    const float* sc = g_sc + ((size_t)nh << 20);
    const float* V = g_v + (size_t)nh * SSQ * HDIM;

#pragma unroll
    for (int j = 0; j < 4; j++)
        cinv[t + 256 * j] = 1.f / g_csum[nh * SSQ + t + 256 * j];

    float D[2][4][4] = {};
    float rsum0 = 0.f, rsum1 = 0.f;

    const int wr = t >> 2, wq = t & 3;        // w loader: rows wr, wr+64
    const int vs = t >> 3, vq = (t & 7) * 8;  // V loader: row s=vs, cols vq..+8

    float2 wv[2][4];
    float4 va, vb;
#pragma unroll
    for (int j = 0; j < 4; j++) {
        int s = (wq * 4 + j) * 2;
        wv[0][j] = *(const float2*)(sc + (size_t)(l0 + wr) * SSQ + s);
        wv[1][j] = *(const float2*)(sc + (size_t)(l0 + 64 + wr) * SSQ + s);
    }
    va = *(const float4*)(V + (size_t)vs * 64 + vq);
    vb = *(const float4*)(V + (size_t)vs * 64 + vq + 4);

    for (int c = 0; c < 32; c++) {
        const int s0 = c * 32;
        __syncthreads();
#pragma unroll
        for (int rr = 0; rr < 2; rr++) {
            int row = rr * 64 + wr;
#pragma unroll
            for (int j = 0; j < 4; j++) {
                int sp = wq * 4 + j;
                float c0 = cinv[s0 + sp * 2], c1 = cinv[s0 + sp * 2 + 1];
                float w0 = wv[rr][j].x * c0 + 1e-8f;
                float w1 = wv[rr][j].y * c1 + 1e-8f;
                if (rr == 0) rsum0 += w0 + w1; else rsum1 += w0 + w1;
                unsigned hi, lo;
                split2(w0, w1, hi, lo);
                Wh[row][sp] = hi;
                Wl[row][sp] = lo;
            }
        }
        {
            float vv[8] = {va.x, va.y, va.z, va.w, vb.x, vb.y, vb.z, vb.w};
            unsigned short* ph = (unsigned short*)Vth;
            unsigned short* pl = (unsigned short*)Vtl;
#pragma unroll
            for (int j = 0; j < 8; j++) {
                int d = vq + j;
                __nv_bfloat16 h = __float2bfloat16(vv[j]);
                __nv_bfloat16 l = __float2bfloat16(vv[j] - __bfloat162float(h));
                ph[d * 36 + vs] = __bfloat16_as_ushort(h);
                pl[d * 36 + vs] = __bfloat16_as_ushort(l);
            }
        }
        __syncthreads();
        if (c < 31) {
            int sn = s0 + 32;
#pragma unroll
            for (int j = 0; j < 4; j++) {
                int s = sn + (wq * 4 + j) * 2;
                wv[0][j] = *(const float2*)(sc + (size_t)(l0 + wr) * SSQ + s);
                wv[1][j] = *(const float2*)(sc + (size_t)(l0 + 64 + wr) * SSQ + s);
            }
            va = *(const float4*)(V + (size_t)(sn + vs) * 64 + vq);
            vb = *(const float4*)(V + (size_t)(sn + vs) * 64 + vq + 4);
        }
#pragma unroll
        for (int ks = 0; ks < 2; ks++) {
            unsigned ah[2][4], al_[2][4];
#pragma unroll
            for (int mt = 0; mt < 2; mt++) {
                int m = wm * 32 + mt * 16 + g;
                ah[mt][0]  = Wh[m][ks * 8 + tq];
                ah[mt][1]  = Wh[m + 8][ks * 8 + tq];
                ah[mt][2]  = Wh[m][ks * 8 + tq + 4];
                ah[mt][3]  = Wh[m + 8][ks * 8 + tq + 4];
                al_[mt][0] = Wl[m][ks * 8 + tq];
                al_[mt][1] = Wl[m + 8][ks * 8 + tq];
                al_[mt][2] = Wl[m][ks * 8 + tq + 4];
                al_[mt][3] = Wl[m + 8][ks * 8 + tq + 4];
            }
#pragma unroll
            for (int nt = 0; nt < 4; nt++) {
                int n = wn * 32 + nt * 8 + g;
                unsigned bh0 = Vth[n][ks * 8 + tq], bh1 = Vth[n][ks * 8 + tq + 4];
                unsigned bl0 = Vtl[n][ks * 8 + tq], bl1 = Vtl[n][ks * 8 + tq + 4];
#pragma unroll
                for (int mt = 0; mt < 2; mt++) {
                    mma_bf16(D[mt][nt], ah[mt], bh0, bh1);
                    mma_bf16(D[mt][nt], al_[mt], bh0, bh1);
                    mma_bf16(D[mt][nt], ah[mt], bl0, bl1);
                }
            }
        }
    }

    __syncthreads();
    rsp[wr][wq] = rsum0;
    rsp[64 + wr][wq] = rsum1;
    __syncthreads();
    if (t < 128)
        rowinv[t] = 1.f / (rsp[t][0] + rsp[t][1] + rsp[t][2] + rsp[t][3]);
    __syncthreads();

    float* dst = g_attn + (size_t)nh * LL * HDIM;
#pragma unroll
    for (int mt = 0; mt < 2; mt++) {
#pragma unroll
        for (int half = 0; half < 2; half++) {
            int r = wm * 32 + mt * 16 + g + half * 8;
            float inv = rowinv[r];
#pragma unroll
            for (int nt = 0; nt < 4; nt++) {
                int d = wn * 32 + nt * 8 + tq * 2;
                *(float2*)(dst + (size_t)(l0 + r) * 64 + d) = make_float2(
                    D[mt][nt][half * 2 + 0] * inv,
                    D[mt][nt][half * 2 + 1] * inv);
            }
        }
    }
}

// ============================================================================
// K5: memory branch + gate combine (unchanged, known-correct).
// ============================================================================
__global__ __launch_bounds__(256) void attn_mem_kernel(
    const float* __restrict__ kmem, const float* __restrict__ vmem,
    const float* __restrict__ gatew)
{
    const int nh = blockIdx.y;
    const int n = nh >> 3, h = nh & 7;
    const int l0 = blockIdx.x * 64;

    __shared__ float qs[64][68];
    __shared__ float kc[32][68];
    __shared__ float vc[32][68];
    __shared__ float ps[64][34];
    __shared__ float mask_s[256];

    const int t = threadIdx.x;
    const int ty = t >> 4, tx = t & 15;

    {
        int row = t >> 2;
        int dq = (t & 3) * 16;
        const float* qp = g_q + ((size_t)nh * LL + l0 + row) * HDIM + dq;
#pragma unroll
        for (int j = 0; j < 4; j++)
            *(float4*)(&qs[row][dq + j * 4]) = *(const float4*)(qp + j * 4);
    }
    mask_s[t] = g_mask[n * MMEM + t] ? 1.f : 0.f;
    __syncthreads();

    float acc2[4][4] = {};
    float rsum[4] = {0.f, 0.f, 0.f, 0.f};

    const int mrow = t >> 3, mq = (t & 7) * 8;

    for (int m0 = 0; m0 < MMEM; m0 += 32) {
        const float* kp = kmem + ((size_t)(m0 + mrow) * NBATCH + n) * EDIM + h * 64 + mq;
        const float* vp = vmem + ((size_t)(m0 + mrow) * NBATCH + n) * EDIM + h * 64 + mq;
        float4 kv0 = *(const float4*)(kp);
        float4 kv1 = *(const float4*)(kp + 4);
        float4 vv0 = *(const float4*)(vp);
        float4 vv1 = *(const float4*)(vp + 4);
        __syncthreads();
        *(float4*)(&kc[mrow][mq])     = kv0;
        *(float4*)(&kc[mrow][mq + 4]) = kv1;
        *(float4*)(&vc[mrow][mq])     = vv0;
        *(float4*)(&vc[mrow][mq + 4]) = vv1;
        __syncthreads();

        float a1[4][2] = {};
#pragma unroll
        for (int kk = 0; kk < 64; kk += 4) {
            float4 b0 = *(const float4*)(&kc[tx * 2][kk]);
            float4 b1 = *(const float4*)(&kc[tx * 2 + 1][kk]);
#pragma unroll
            for (int i = 0; i < 4; i++) {
                float4 a = *(const float4*)(&qs[ty * 4 + i][kk]);
                a1[i][0] = fmaf(a.x, b0.x, fmaf(a.y, b0.y,
                           fmaf(a.z, b0.z, fmaf(a.w, b0.w, a1[i][0]))));
                a1[i][1] = fmaf(a.x, b1.x, fmaf(a.y, b1.y,
                           fmaf(a.z, b1.z, fmaf(a.w, b1.w, a1[i][1]))));
            }
        }
        float msk0 = mask_s[m0 + tx * 2];
        float msk1 = mask_s[m0 + tx * 2 + 1];
#pragma unroll
        for (int i = 0; i < 4; i++) {
            float p0 = (msk0 != 0.f) ? 0.f : __expf(a1[i][0]);
            float p1 = (msk1 != 0.f) ? 0.f : __expf(a1[i][1]);
            ps[ty * 4 + i][tx * 2]     = p0;
            ps[ty * 4 + i][tx * 2 + 1] = p1;
            rsum[i] += p0 + p1;
        }
        __syncthreads();

#pragma unroll
        for (int kk = 0; kk < 32; kk++) {
            float4 b = *(const float4*)(&vc[kk][tx * 4]);
#pragma unroll
            for (int i = 0; i < 4; i++) {
                float a = ps[ty * 4 + i][kk];
                acc2[i][0] = fmaf(a, b.x, acc2[i][0]);
                acc2[i][1] = fmaf(a, b.y, acc2[i][1]);
                acc2[i][2] = fmaf(a, b.z, acc2[i][2]);
                acc2[i][3] = fmaf(a, b.w, acc2[i][3]);
            }
        }
    }

#pragma unroll
    for (int i = 0; i < 4; i++) {
        float r = rsum[i];
        r += __shfl_xor_sync(0xffffffffu, r, 8);
        r += __shfl_xor_sync(0xffffffffu, r, 4);
        r += __shfl_xor_sync(0xffffffffu, r, 2);
        r += __shfl_xor_sync(0xffffffffu, r, 1);
        rsum[i] = r;
    }

    const float gate = 1.f / (1.f + __expf(-gatew[h]));
    const float omg = 1.f - gate;
#pragma unroll
    for (int i = 0; i < 4; i++) {
        int l = l0 + ty * 4 + i;
        float inv = 1.f / rsum[i];
        float4 am = *(const float4*)(g_attn + ((size_t)nh * LL + l) * 64 + tx * 4);
        float4 o;
        o.x = gate * (acc2[i][0] * inv) + omg * am.x;
        o.y = gate * (acc2[i][1] * inv) + omg * am.y;
        o.z = gate * (acc2[i][2] * inv) + omg * am.z;
        o.w = gate * (acc2[i][3] * inv) + omg * am.w;
        *(float4*)(g_ctx + ((size_t)l * NBATCH + n) * EDIM + h * 64 + tx * 4) = o;
    }
}

// ============================================================================
extern "C" void kernel_launch(void* const* d_in, const int* in_sizes, int n_in,
                              void* d_out, int out_size)
{
    const float* query = (const float*)d_in[0];
    const float* key   = (const float*)d_in[1];
    const float* value = (const float*)d_in[2];
    const float* Wi    = (const float*)d_in[3];
    const float* Bi    = (const float*)d_in[4];
    const float* Wo    = (const float*)d_in[5];
    const float* Bo    = (const float*)d_in[6];
    const float* rq    = (const float*)d_in[7];
    const float* rk    = (const float*)d_in[8];
    const float* kmem  = (const float*)d_in[9];
    const float* vmem  = (const float*)d_in[10];
    const float* gate  = (const float*)d_in[11];
    const unsigned int* mmask_raw = (const unsigned int*)d_in[12];
    float* out = (float*)d_out;

    mask_decode_kernel<<<1, 256>>>(mmask_raw);
    proj_mma<<<dim3(4, 64, 3), 256>>>(query, key, value, Wi, Bi, Wo, Bo,
                                      rq, rk, out, 0);
    scores_mma<<<dim3(8, 8, 64), 256>>>();
    colsum2_kernel<<<dim3(4, 64), 256>>>();
    attn_main_mma<<<dim3(8, 64), 256>>>();
    attn_mem_kernel<<<dim3(16, 64), 256>>>(kmem, vmem, gate);
    proj_mma<<<dim3(4, 64, 1), 256>>>(query, key, value, Wi, Bi, Wo, Bo,
                                      rq, rk, out, 3);
}

// round 14
// speedup vs baseline: 1.3691x; 1.0134x over previous
#include <cuda_runtime.h>
#include <cuda_bf16.h>

#define LL     1024
#define SSQ    1024
#define MMEM   256
#define NBATCH 8
#define EDIM   512
#define NHEAD  8
#define HDIM   64
#define NH     64
#define RTOT   8192

// fp32 state
static __device__ __align__(16) float g_q[NH * LL * HDIM];
static __device__ __align__(16) float g_v[NH * SSQ * HDIM];
static __device__ __align__(16) float g_cpart[NH * 8 * SSQ];
static __device__ __align__(16) float g_csum[NH * SSQ];
static __device__ __align__(16) float g_attn[NH * LL * HDIM];
static __device__ __align__(16) float g_sv[NH * HDIM];
static __device__ unsigned char g_mask[NBATCH * MMEM];
// split bf16 planes
static __device__ __align__(16) unsigned short g_xh[3 * RTOT * EDIM];
static __device__ __align__(16) unsigned short g_xl[3 * RTOT * EDIM];
static __device__ __align__(16) unsigned short g_wsh[4 * EDIM * EDIM];
static __device__ __align__(16) unsigned short g_wsl[4 * EDIM * EDIM];
static __device__ __align__(16) unsigned short g_qh[NH * LL * HDIM];
static __device__ __align__(16) unsigned short g_ql[NH * LL * HDIM];
static __device__ __align__(16) unsigned short g_kh[NH * SSQ * HDIM];
static __device__ __align__(16) unsigned short g_kl[NH * SSQ * HDIM];
static __device__ __align__(16) unsigned short g_sch[(size_t)NH * LL * SSQ];
static __device__ __align__(16) unsigned short g_scl[(size_t)NH * LL * SSQ];
static __device__ __align__(16) unsigned short g_ctxh[RTOT * EDIM];
static __device__ __align__(16) unsigned short g_ctxl[RTOT * EDIM];

__device__ __forceinline__ void mma_bf16(float* d, const unsigned* a,
                                         unsigned b0, unsigned b1) {
    asm volatile(
        "mma.sync.aligned.m16n8k16.row.col.f32.bf16.bf16.f32 "
        "{%0,%1,%2,%3},{%4,%5,%6,%7},{%8,%9},{%0,%1,%2,%3};\n"
        : "+f"(d[0]), "+f"(d[1]), "+f"(d[2]), "+f"(d[3])
        : "r"(a[0]), "r"(a[1]), "r"(a[2]), "r"(a[3]), "r"(b0), "r"(b1));
}

__device__ __forceinline__ void split2(float x, float y,
                                       unsigned &hi, unsigned &lo) {
    unsigned h;
    asm("cvt.rn.bf16x2.f32 %0, %1, %2;" : "=r"(h) : "f"(y), "f"(x));
    __nv_bfloat162 hb = *reinterpret_cast<__nv_bfloat162*>(&h);
    float rx = x - __bfloat162float(hb.x);
    float ry = y - __bfloat162float(hb.y);
    unsigned l;
    asm("cvt.rn.bf16x2.f32 %0, %1, %2;" : "=r"(l) : "f"(ry), "f"(rx));
    hi = h; lo = l;
}

// ============================================================================
// K0a: decode mem_mask regardless of upload encoding.
__global__ __launch_bounds__(256) void mask_decode_kernel(
    const unsigned int* __restrict__ m)
{
    __shared__ int enc_flags;
    if (threadIdx.x == 0) enc_flags = 0;
    __syncthreads();
    for (int i = threadIdx.x; i < 512; i += 256) {
        unsigned int w = m[i];
        if ((w & 0xFFFFu) == 0x3F80u) atomicOr(&enc_flags, 2);
        else if ((w >> 8) != 0 && w != 0x3F800000u) atomicOr(&enc_flags, 1);
    }
    __syncthreads();
    int f = enc_flags;
    if (f & 2) {
        const unsigned short* mh = (const unsigned short*)m;
        for (int i = threadIdx.x; i < NBATCH * MMEM; i += 256)
            g_mask[i] = mh[i] ? 1 : 0;
    } else if (f & 1) {
        const unsigned char* mb = (const unsigned char*)m;
        for (int i = threadIdx.x; i < NBATCH * MMEM; i += 256)
            g_mask[i] = mb[i] ? 1 : 0;
    } else {
        for (int i = threadIdx.x; i < NBATCH * MMEM; i += 256)
            g_mask[i] = m[i] ? 1 : 0;
    }
}

// K0b: pre-split fp32 -> bf16 hi/lo planes. dst_sel 0 = X planes, 1 = W planes.
__global__ __launch_bounds__(256) void split_kernel(
    const float* __restrict__ src, int dst_sel, size_t dst_off, int n2)
{
    unsigned* dh = (unsigned*)((dst_sel == 0 ? g_xh : g_wsh) + dst_off);
    unsigned* dl = (unsigned*)((dst_sel == 0 ? g_xl : g_wsl) + dst_off);
    for (int i = blockIdx.x * 256 + threadIdx.x; i < n2; i += gridDim.x * 256) {
        float2 v = ((const float2*)src)[i];
        unsigned hi, lo;
        split2(v.x, v.y, hi, lo);
        dh[i] = hi; dl[i] = lo;
    }
}

// K0c: g_sv[nh][d] = sum_s v[nh][s][d]
__global__ __launch_bounds__(256) void vsum_kernel()
{
    __shared__ float p[4][64];
    int nh = blockIdx.x, d = threadIdx.x & 63, sg = threadIdx.x >> 6;
    const float* V = g_v + (size_t)nh * SSQ * HDIM;
    float s = 0.f;
    for (int ss = sg; ss < SSQ; ss += 4) s += V[(size_t)ss * 64 + d];
    p[sg][d] = s;
    __syncthreads();
    if (threadIdx.x < 64)
        g_sv[nh * 64 + threadIdx.x] = p[0][threadIdx.x] + p[1][threadIdx.x] +
                                      p[2][threadIdx.x] + p[3][threadIdx.x];
}

// ============================================================================
// K1: unified projection GEMM, 3-pass split-bf16 mma, staging = pure copies
// from pre-split planes. mode 0/1/2 = q/k/v, mode 3 = out-proj.
// ============================================================================
__global__ __launch_bounds__(256, 1) void proj_mma(
    const float* __restrict__ Bi, const float* __restrict__ Bo,
    const float* __restrict__ rq, const float* __restrict__ rk,
    float* __restrict__ out, int base_mode)
{
    const int mode = base_mode + blockIdx.z;
    const unsigned* APh = (const unsigned*)(mode < 3 ?
        g_xh + (size_t)mode * RTOT * EDIM : g_ctxh);
    const unsigned* APl = (const unsigned*)(mode < 3 ?
        g_xl + (size_t)mode * RTOT * EDIM : g_ctxl);
    const unsigned* BPh = (const unsigned*)(g_wsh + (size_t)mode * EDIM * EDIM);
    const unsigned* BPl = (const unsigned*)(g_wsl + (size_t)mode * EDIM * EDIM);
    const float* Bm = (mode < 3) ? Bi + mode * EDIM : Bo;
    const float* rot = (mode == 0) ? rq : rk;

    __shared__ unsigned Ah[128][20], Al[128][20], Bh[128][20], Bl[128][20];

    const int t = threadIdx.x;
    const int warp = t >> 5, lane = t & 31;
    const int g = lane >> 2, tq = lane & 3;
    const int wm = warp >> 1, wn = warp & 1;
    const int row0 = blockIdx.y * 128, col0 = blockIdx.x * 128;
    const int sr = t >> 2, sc4 = (t & 3) * 4;   // staging row/col

    float D[2][8][4] = {};
    uint4 rah[2], ral[2], rbh[2], rbl[2];

#pragma unroll
    for (int j = 0; j < 2; j++) {
        int r = sr + j * 64;
        size_t ao = (size_t)(row0 + r) * 256 + sc4;
        size_t bo = (size_t)(col0 + r) * 256 + sc4;
        rah[j] = *(const uint4*)(APh + ao);
        ral[j] = *(const uint4*)(APl + ao);
        rbh[j] = *(const uint4*)(BPh + bo);
        rbl[j] = *(const uint4*)(BPl + bo);
    }

    for (int kc = 0; kc < 16; kc++) {
        __syncthreads();
#pragma unroll
        for (int j = 0; j < 2; j++) {
            int r = sr + j * 64;
            *(uint4*)&Ah[r][sc4] = rah[j];
            *(uint4*)&Al[r][sc4] = ral[j];
            *(uint4*)&Bh[r][sc4] = rbh[j];
            *(uint4*)&Bl[r][sc4] = rbl[j];
        }
        __syncthreads();
        if (kc < 15) {
#pragma unroll
            for (int j = 0; j < 2; j++) {
                int r = sr + j * 64;
                size_t ao = (size_t)(row0 + r) * 256 + (kc + 1) * 16 + sc4;
                size_t bo = (size_t)(col0 + r) * 256 + (kc + 1) * 16 + sc4;
                rah[j] = *(const uint4*)(APh + ao);
                ral[j] = *(const uint4*)(APl + ao);
                rbh[j] = *(const uint4*)(BPh + bo);
                rbl[j] = *(const uint4*)(BPl + bo);
            }
        }
#pragma unroll
        for (int ks = 0; ks < 2; ks++) {
            unsigned ah[2][4], al_[2][4];
#pragma unroll
            for (int mt = 0; mt < 2; mt++) {
                int m = wm * 32 + mt * 16 + g;
                ah[mt][0]  = Ah[m][ks * 8 + tq];
                ah[mt][1]  = Ah[m + 8][ks * 8 + tq];
                ah[mt][2]  = Ah[m][ks * 8 + tq + 4];
                ah[mt][3]  = Ah[m + 8][ks * 8 + tq + 4];
                al_[mt][0] = Al[m][ks * 8 + tq];
                al_[mt][1] = Al[m + 8][ks * 8 + tq];
                al_[mt][2] = Al[m][ks * 8 + tq + 4];
                al_[mt][3] = Al[m + 8][ks * 8 + tq + 4];
            }
#pragma unroll
            for (int nt = 0; nt < 8; nt++) {
                int n = wn * 64 + nt * 8 + g;
                unsigned bh0 = Bh[n][ks * 8 + tq], bh1 = Bh[n][ks * 8 + tq + 4];
                unsigned bl0 = Bl[n][ks * 8 + tq], bl1 = Bl[n][ks * 8 + tq + 4];
#pragma unroll
                for (int mt = 0; mt < 2; mt++) {
                    mma_bf16(D[mt][nt], ah[mt], bh0, bh1);
                    mma_bf16(D[mt][nt], ah[mt], bl0, bl1);
                    mma_bf16(D[mt][nt], al_[mt], bh0, bh1);
                }
            }
        }
    }

    const float scale = (mode == 0) ? 0.125f : 1.0f;
#pragma unroll
    for (int mt = 0; mt < 2; mt++) {
#pragma unroll
        for (int half = 0; half < 2; half++) {
            int r = row0 + wm * 32 + mt * 16 + g + half * 8;
#pragma unroll
            for (int nt = 0; nt < 8; nt++) {
                int c = col0 + wn * 64 + nt * 8 + tq * 2;
                float v0 = D[mt][nt][half * 2 + 0] + Bm[c];
                float v1 = D[mt][nt][half * 2 + 1] + Bm[c + 1];
                if (mode == 3) {
                    *(float2*)(out + (size_t)r * EDIM + c) = make_float2(v0, v1);
                } else if (mode == 2) {
                    int l = r >> 3, nn = r & 7;
                    *(float2*)(g_v + (size_t)((nn * NHEAD + (c >> 6)) * LL + l)
                               * HDIM + (c & 63)) = make_float2(v0, v1);
                } else {
                    v0 *= scale; v1 *= scale;
                    int l = r >> 3, nn = r & 7;
                    const float* rp = rot + ((size_t)(nn * LL + l) * EDIM + c) * 2;
                    float4 rr = *(const float4*)rp;
                    float o0 = v0 * rr.x - v1 * rr.y;
                    float o1 = v1 * rr.z + v0 * rr.w;
                    size_t off = (size_t)((nn * NHEAD + (c >> 6)) * LL + l)
                                 * HDIM + (c & 63);
                    unsigned ph, pl;
                    split2(o0, o1, ph, pl);
                    if (mode == 0) {
                        *(float2*)(g_q + off) = make_float2(o0, o1);
                        ((unsigned*)g_qh)[off >> 1] = ph;
                        ((unsigned*)g_ql)[off >> 1] = pl;
                    } else {
                        ((unsigned*)g_kh)[off >> 1] = ph;
                        ((unsigned*)g_kl)[off >> 1] = pl;
                    }
                }
            }
        }
    }
}

// ============================================================================
// K2: exp(scores) via 3-pass split-bf16 mma (QhKh + QlKh + QhKl), staging =
// pure uint4 copies. Output: split bf16 planes + col partials.
// ============================================================================
__global__ __launch_bounds__(256, 1) void scores_mma()
{
    __shared__ unsigned X[128][36], Y[128][36];
    __shared__ float red[8][64];

    const int nh = blockIdx.z;
    const int l0 = blockIdx.y * 128, s0 = blockIdx.x * 128;
    const int t = threadIdx.x;
    const int warp = t >> 5, lane = t & 31;
    const int g = lane >> 2, tq = lane & 3;
    const int wm = warp >> 1, wn = warp & 1;

    const unsigned* QH = (const unsigned*)g_qh + ((size_t)nh * LL + l0) * 32;
    const unsigned* QL = (const unsigned*)g_ql + ((size_t)nh * LL + l0) * 32;
    const unsigned* KH = (const unsigned*)g_kh + ((size_t)nh * SSQ + s0) * 32;
    const unsigned* KL = (const unsigned*)g_kl + ((size_t)nh * SSQ + s0) * 32;

    float D[2][8][4] = {};

    auto stageP = [&](unsigned (*buf)[36], const unsigned* src) {
#pragma unroll
        for (int j = 0; j < 4; j++) {
            int idx = t + 256 * j, r = idx >> 3, q4 = idx & 7;
            *(uint4*)&buf[r][q4 * 4] = *(const uint4*)(src + (size_t)r * 32 + q4 * 4);
        }
    };
    auto do_pass = [&]() {
#pragma unroll
        for (int ks = 0; ks < 4; ks++) {
            unsigned a[2][4];
#pragma unroll
            for (int mt = 0; mt < 2; mt++) {
                int m = wm * 32 + mt * 16 + g;
                a[mt][0] = X[m][ks * 8 + tq];
                a[mt][1] = X[m + 8][ks * 8 + tq];
                a[mt][2] = X[m][ks * 8 + tq + 4];
                a[mt][3] = X[m + 8][ks * 8 + tq + 4];
            }
#pragma unroll
            for (int nt = 0; nt < 8; nt++) {
                int n = wn * 64 + nt * 8 + g;
                unsigned b0 = Y[n][ks * 8 + tq], b1 = Y[n][ks * 8 + tq + 4];
#pragma unroll
                for (int mt = 0; mt < 2; mt++)
                    mma_bf16(D[mt][nt], a[mt], b0, b1);
            }
        }
    };

    stageP(X, QH); stageP(Y, KH);
    __syncthreads(); do_pass();          // qh*kh
    __syncthreads(); stageP(X, QL);
    __syncthreads(); do_pass();          // ql*kh
    __syncthreads(); stageP(X, QH); stageP(Y, KL);
    __syncthreads(); do_pass();          // qh*kl

    unsigned* SCH = (unsigned*)g_sch + ((size_t)nh << 19);
    unsigned* SCL = (unsigned*)g_scl + ((size_t)nh << 19);
    float cs[8][2] = {};
#pragma unroll
    for (int mt = 0; mt < 2; mt++) {
#pragma unroll
        for (int half = 0; half < 2; half++) {
            int l = l0 + wm * 32 + mt * 16 + g + half * 8;
#pragma unroll
            for (int nt = 0; nt < 8; nt++) {
                int s = s0 + wn * 64 + nt * 8 + tq * 2;
                float e0 = __expf(D[mt][nt][half * 2 + 0]);
                float e1 = __expf(D[mt][nt][half * 2 + 1]);
                unsigned hi, lo;
                split2(e0, e1, hi, lo);
                size_t ui = (size_t)l * 512 + (s >> 1);
                SCH[ui] = hi; SCL[ui] = lo;
                cs[nt][0] += e0;
                cs[nt][1] += e1;
            }
        }
    }
#pragma unroll
    for (int nt = 0; nt < 8; nt++) {
#pragma unroll
        for (int c2 = 0; c2 < 2; c2++) {
            float v = cs[nt][c2];
            v += __shfl_xor_sync(0xffffffffu, v, 4);
            v += __shfl_xor_sync(0xffffffffu, v, 8);
            v += __shfl_xor_sync(0xffffffffu, v, 16);
            if (g == 0) red[warp][nt * 8 + tq * 2 + c2] = v;
        }
    }
    __syncthreads();
    if (t < 128) {
        int wnn = t >> 6, cc = t & 63;
        float tot = red[wnn][cc] + red[wnn + 2][cc] +
                    red[wnn + 4][cc] + red[wnn + 6][cc];
        g_cpart[((size_t)nh * 8 + blockIdx.y) * SSQ + s0 + t] = tot;
    }
}

// ============================================================================
// K3: reduce 8 column partials -> g_csum.
__global__ __launch_bounds__(256) void colsum2_kernel()
{
    int nh = blockIdx.y, s = blockIdx.x * 256 + threadIdx.x;
    float sum = 0.f;
#pragma unroll
    for (int j = 0; j < 8; j++)
        sum += g_cpart[((size_t)nh * 8 + j) * SSQ + s];
    g_csum[nh * SSQ + s] = sum;
}

// ============================================================================
// K4: main attention: attn = (sc @ (cinv*V) + 1e-8*sv) / (rowsum + 1.024e-5).
// sc loaded as split bf16 planes (pure copies); rowsum via cheap fp32 dot.
// ============================================================================
__global__ __launch_bounds__(256, 1) void attn_main_mma()
{
    __shared__ unsigned Wh[128][20], Wl[128][20];
    __shared__ unsigned Vth[64][18], Vtl[64][18];
    __shared__ float cinv[1024];
    __shared__ float rsp[128][4];
    __shared__ float rowinv[128];

    const int nh = blockIdx.y, l0 = blockIdx.x * 128;
    const int t = threadIdx.x;
    const int warp = t >> 5, lane = t & 31;
    const int g = lane >> 2, tq = lane & 3;
    const int wm = warp >> 1, wn = warp & 1;

    const unsigned* SH = (const unsigned*)g_sch + ((size_t)nh << 19);
    const unsigned* SL = (const unsigned*)g_scl + ((size_t)nh << 19);
    const float* V = g_v + (size_t)nh * SSQ * HDIM;

#pragma unroll
    for (int j = 0; j < 4; j++)
        cinv[t + 256 * j] = 1.f / g_csum[nh * SSQ + t + 256 * j];

    float D[2][4][4] = {};
    float rsum0 = 0.f, rsum1 = 0.f;

    const int wr = t >> 2, wq = t & 3;        // w loader
    const int vs = t >> 3, vq = (t & 7) * 8;  // V loader

    uint4 wh0, wl0, wh1, wl1;
    float4 va, vb;
    wh0 = *(const uint4*)(SH + (size_t)(l0 + wr) * 512 + wq * 4);
    wl0 = *(const uint4*)(SL + (size_t)(l0 + wr) * 512 + wq * 4);
    wh1 = *(const uint4*)(SH + (size_t)(l0 + 64 + wr) * 512 + wq * 4);
    wl1 = *(const uint4*)(SL + (size_t)(l0 + 64 + wr) * 512 + wq * 4);
    va = *(const float4*)(V + (size_t)vs * 64 + vq);
    vb = *(const float4*)(V + (size_t)vs * 64 + vq + 4);
    __syncthreads();   // cinv ready

    for (int c = 0; c < 32; c++) {
        const int s0 = c * 32;
#pragma unroll
        for (int rr = 0; rr < 2; rr++) {
            uint4 H = rr ? wh1 : wh0, L = rr ? wl1 : wl0;
            int row = rr * 64 + wr;
            *(uint4*)&Wh[row][wq * 4] = H;
            *(uint4*)&Wl[row][wq * 4] = L;
            const unsigned* hp = (const unsigned*)&H;
            const unsigned* lp = (const unsigned*)&L;
            float rs = 0.f;
#pragma unroll
            for (int u = 0; u < 4; u++) {
                float2 h2 = __bfloat1622float2(
                    *(const __nv_bfloat162*)&hp[u]);
                float2 l2 = __bfloat1622float2(
                    *(const __nv_bfloat162*)&lp[u]);
                int s = s0 + wq * 8 + u * 2;
                rs += (h2.x + l2.x) * cinv[s] + (h2.y + l2.y) * cinv[s + 1];
            }
            if (rr == 0) rsum0 += rs; else rsum1 += rs;
        }
        {
            float cv = cinv[s0 + vs];
            float vv[8] = {va.x * cv, va.y * cv, va.z * cv, va.w * cv,
                           vb.x * cv, vb.y * cv, vb.z * cv, vb.w * cv};
            unsigned short* ph = (unsigned short*)Vth;
            unsigned short* pl = (unsigned short*)Vtl;
#pragma unroll
            for (int j = 0; j < 8; j++) {
                int d = vq + j;
                __nv_bfloat16 h = __float2bfloat16(vv[j]);
                __nv_bfloat16 l = __float2bfloat16(vv[j] - __bfloat162float(h));
                ph[d * 36 + vs] = __bfloat16_as_ushort(h);
                pl[d * 36 + vs] = __bfloat16_as_ushort(l);
            }
        }
        __syncthreads();
        if (c < 31) {
            int sn = s0 + 32;
            wh0 = *(const uint4*)(SH + (size_t)(l0 + wr) * 512 + sn / 2 + wq * 4);
            wl0 = *(const uint4*)(SL + (size_t)(l0 + wr) * 512 + sn / 2 + wq * 4);
            wh1 = *(const uint4*)(SH + (size_t)(l0 + 64 + wr) * 512 + sn / 2 + wq * 4);
            wl1 = *(const uint4*)(SL + (size_t)(l0 + 64 + wr) * 512 + sn / 2 + wq * 4);
            va = *(const float4*)(V + (size_t)(sn + vs) * 64 + vq);
            vb = *(const float4*)(V + (size_t)(sn + vs) * 64 + vq + 4);
        }
#pragma unroll
        for (int ks = 0; ks < 2; ks++) {
            unsigned ah[2][4], al_[2][4];
#pragma unroll
            for (int mt = 0; mt < 2; mt++) {
                int m = wm * 32 + mt * 16 + g;
                ah[mt][0]  = Wh[m][ks * 8 + tq];
                ah[mt][1]  = Wh[m + 8][ks * 8 + tq];
                ah[mt][2]  = Wh[m][ks * 8 + tq + 4];
                ah[mt][3]  = Wh[m + 8][ks * 8 + tq + 4];
                al_[mt][0] = Wl[m][ks * 8 + tq];
                al_[mt][1] = Wl[m + 8][ks * 8 + tq];
                al_[mt][2] = Wl[m][ks * 8 + tq + 4];
                al_[mt][3] = Wl[m + 8][ks * 8 + tq + 4];
            }
#pragma unroll
            for (int nt = 0; nt < 4; nt++) {
                int n = wn * 32 + nt * 8 + g;
                unsigned bh0 = Vth[n][ks * 8 + tq], bh1 = Vth[n][ks * 8 + tq + 4];
                unsigned bl0 = Vtl[n][ks * 8 + tq], bl1 = Vtl[n][ks * 8 + tq + 4];
#pragma unroll
                for (int mt = 0; mt < 2; mt++) {
                    mma_bf16(D[mt][nt], ah[mt], bh0, bh1);
                    mma_bf16(D[mt][nt], al_[mt], bh0, bh1);
                    mma_bf16(D[mt][nt], ah[mt], bl0, bl1);
                }
            }
        }
        __syncthreads();
    }

    rsp[wr][wq] = rsum0;
    rsp[64 + wr][wq] = rsum1;
    __syncthreads();
    if (t < 128)
        rowinv[t] = 1.f / (rsp[t][0] + rsp[t][1] + rsp[t][2] + rsp[t][3]
                           + 1.024e-5f);
    __syncthreads();

    float* dst = g_attn + (size_t)nh * LL * HDIM;
    const float* sv = g_sv + nh * 64;
#pragma unroll
    for (int mt = 0; mt < 2; mt++) {
#pragma unroll
        for (int half = 0; half < 2; half++) {
            int r = wm * 32 + mt * 16 + g + half * 8;
            float inv = rowinv[r];
#pragma unroll
            for (int nt = 0; nt < 4; nt++) {
                int d = wn * 32 + nt * 8 + tq * 2;
                *(float2*)(dst + (size_t)(l0 + r) * 64 + d) = make_float2(
                    (D[mt][nt][half * 2 + 0] + 1e-8f * sv[d]) * inv,
                    (D[mt][nt][half * 2 + 1] + 1e-8f * sv[d + 1]) * inv);
            }
        }
    }
}

// ============================================================================
// K5: memory branch + gate combine; writes ctx as split bf16 planes.
// ============================================================================
__global__ __launch_bounds__(256) void attn_mem_kernel(
    const float* __restrict__ kmem, const float* __restrict__ vmem,
    const float* __restrict__ gatew)
{
    const int nh = blockIdx.y;
    const int n = nh >> 3, h = nh & 7;
    const int l0 = blockIdx.x * 64;

    __shared__ float qs[64][68];
    __shared__ float kc[32][68];
    __shared__ float vc[32][68];
    __shared__ float ps[64][34];
    __shared__ float mask_s[256];

    const int t = threadIdx.x;
    const int ty = t >> 4, tx = t & 15;

    {
        int row = t >> 2;
        int dq = (t & 3) * 16;
        const float* qp = g_q + ((size_t)nh * LL + l0 + row) * HDIM + dq;
#pragma unroll
        for (int j = 0; j < 4; j++)
            *(float4*)(&qs[row][dq + j * 4]) = *(const float4*)(qp + j * 4);
    }
    mask_s[t] = g_mask[n * MMEM + t] ? 1.f : 0.f;
    __syncthreads();

    float acc2[4][4] = {};
    float rsum[4] = {0.f, 0.f, 0.f, 0.f};

    const int mrow = t >> 3, mq = (t & 7) * 8;

    for (int m0 = 0; m0 < MMEM; m0 += 32) {
        const float* kp = kmem + ((size_t)(m0 + mrow) * NBATCH + n) * EDIM + h * 64 + mq;
        const float* vp = vmem + ((size_t)(m0 + mrow) * NBATCH + n) * EDIM + h * 64 + mq;
        float4 kv0 = *(const float4*)(kp);
        float4 kv1 = *(const float4*)(kp + 4);
        float4 vv0 = *(const float4*)(vp);
        float4 vv1 = *(const float4*)(vp + 4);
        __syncthreads();
        *(float4*)(&kc[mrow][mq])     = kv0;
        *(float4*)(&kc[mrow][mq + 4]) = kv1;
        *(float4*)(&vc[mrow][mq])     = vv0;
        *(float4*)(&vc[mrow][mq + 4]) = vv1;
        __syncthreads();

        float a1[4][2] = {};
#pragma unroll
        for (int kk = 0; kk < 64; kk += 4) {
            float4 b0 = *(const float4*)(&kc[tx * 2][kk]);
            float4 b1 = *(const float4*)(&kc[tx * 2 + 1][kk]);
#pragma unroll
            for (int i = 0; i < 4; i++) {
                float4 a = *(const float4*)(&qs[ty * 4 + i][kk]);
                a1[i][0] = fmaf(a.x, b0.x, fmaf(a.y, b0.y,
                           fmaf(a.z, b0.z, fmaf(a.w, b0.w, a1[i][0]))));
                a1[i][1] = fmaf(a.x, b1.x, fmaf(a.y, b1.y,
                           fmaf(a.z, b1.z, fmaf(a.w, b1.w, a1[i][1]))));
            }
        }
        float msk0 = mask_s[m0 + tx * 2];
        float msk1 = mask_s[m0 + tx * 2 + 1];
#pragma unroll
        for (int i = 0; i < 4; i++) {
            float p0 = (msk0 != 0.f) ? 0.f : __expf(a1[i][0]);
            float p1 = (msk1 != 0.f) ? 0.f : __expf(a1[i][1]);
            ps[ty * 4 + i][tx * 2]     = p0;
            ps[ty * 4 + i][tx * 2 + 1] = p1;
            rsum[i] += p0 + p1;
        }
        __syncthreads();

#pragma unroll
        for (int kk = 0; kk < 32; kk++) {
            float4 b = *(const float4*)(&vc[kk][tx * 4]);
#pragma unroll
            for (int i = 0; i < 4; i++) {
                float a = ps[ty * 4 + i][kk];
                acc2[i][0] = fmaf(a, b.x, acc2[i][0]);
                acc2[i][1] = fmaf(a, b.y, acc2[i][1]);
                acc2[i][2] = fmaf(a, b.z, acc2[i][2]);
                acc2[i][3] = fmaf(a, b.w, acc2[i][3]);
            }
        }
    }

#pragma unroll
    for (int i = 0; i < 4; i++) {
        float r = rsum[i];
        r += __shfl_xor_sync(0xffffffffu, r, 8);
        r += __shfl_xor_sync(0xffffffffu, r, 4);
        r += __shfl_xor_sync(0xffffffffu, r, 2);
        r += __shfl_xor_sync(0xffffffffu, r, 1);
        rsum[i] = r;
    }

    const float gate = 1.f / (1.f + __expf(-gatew[h]));
    const float omg = 1.f - gate;
#pragma unroll
    for (int i = 0; i < 4; i++) {
        int l = l0 + ty * 4 + i;
        float inv = 1.f / rsum[i];
        float4 am = *(const float4*)(g_attn + ((size_t)nh * LL + l) * 64 + tx * 4);
        float o0 = gate * (acc2[i][0] * inv) + omg * am.x;
        float o1 = gate * (acc2[i][1] * inv) + omg * am.y;
        float o2 = gate * (acc2[i][2] * inv) + omg * am.z;
        float o3 = gate * (acc2[i][3] * inv) + omg * am.w;
        unsigned h0, l0v, h1, l1v;
        split2(o0, o1, h0, l0v);
        split2(o2, o3, h1, l1v);
        size_t ui = (((size_t)l * NBATCH + n) * EDIM + h * 64 + tx * 4) >> 1;
        *(uint2*)((unsigned*)g_ctxh + ui) = make_uint2(h0, h1);
        *(uint2*)((unsigned*)g_ctxl + ui) = make_uint2(l0v, l1v);
    }
}

// ============================================================================
extern "C" void kernel_launch(void* const* d_in, const int* in_sizes, int n_in,
                              void* d_out, int out_size)
{
    const float* query = (const float*)d_in[0];
    const float* key   = (const float*)d_in[1];
    const float* value = (const float*)d_in[2];
    const float* Bi    = (const float*)d_in[4];
    const float* Wo    = (const float*)d_in[5];
    const float* Bo    = (const float*)d_in[6];
    const float* rq    = (const float*)d_in[7];
    const float* rk    = (const float*)d_in[8];
    const float* kmem  = (const float*)d_in[9];
    const float* vmem  = (const float*)d_in[10];
    const float* gate  = (const float*)d_in[11];
    const float* Wi    = (const float*)d_in[3];
    const unsigned int* mmask_raw = (const unsigned int*)d_in[12];
    float* out = (float*)d_out;

    const int NX2 = RTOT * EDIM / 2;          // 2,097,152 pairs
    const int NW2 = 3 * EDIM * EDIM / 2;      // 393,216
    const int NWO2 = EDIM * EDIM / 2;         // 131,072

    mask_decode_kernel<<<1, 256>>>(mmask_raw);
    split_kernel<<<2048, 256>>>(query, 0, 0, NX2);
    split_kernel<<<2048, 256>>>(key,   0, (size_t)RTOT * EDIM, NX2);
    split_kernel<<<2048, 256>>>(value, 0, (size_t)2 * RTOT * EDIM, NX2);
    split_kernel<<<1024, 256>>>(Wi, 1, 0, NW2);
    split_kernel<<<512, 256>>>(Wo, 1, (size_t)3 * EDIM * EDIM, NWO2);

    proj_mma<<<dim3(4, 64, 3), 256>>>(Bi, Bo, rq, rk, out, 0);
    vsum_kernel<<<64, 256>>>();
    scores_mma<<<dim3(8, 8, 64), 256>>>();
    colsum2_kernel<<<dim3(4, 64), 256>>>();
    attn_main_mma<<<dim3(8, 64), 256>>>();
    attn_mem_kernel<<<dim3(16, 64), 256>>>(kmem, vmem, gate);
    proj_mma<<<dim3(4, 64, 1), 256>>>(Bi, Bo, rq, rk, out, 3);
}

// round 15
// speedup vs baseline: 1.4847x; 1.0845x over previous
#include <cuda_runtime.h>
#include <cuda_bf16.h>

#define LL     1024
#define SSQ    1024
#define MMEM   256
#define NBATCH 8
#define EDIM   512
#define NHEAD  8
#define HDIM   64
#define NH     64
#define RTOT   8192

// fp32 state
static __device__ __align__(16) float g_v[NH * SSQ * HDIM];
static __device__ __align__(16) float g_cpart[NH * 8 * SSQ];
static __device__ __align__(16) float g_csum[NH * SSQ];
static __device__ __align__(16) float g_attn[NH * LL * HDIM];
static __device__ __align__(16) float g_sv[NH * HDIM];
static __device__ unsigned char g_mask[NBATCH * MMEM];
// split bf16 planes
static __device__ __align__(16) unsigned short g_xh[3 * RTOT * EDIM];
static __device__ __align__(16) unsigned short g_xl[3 * RTOT * EDIM];
static __device__ __align__(16) unsigned short g_wsh[4 * EDIM * EDIM];
static __device__ __align__(16) unsigned short g_wsl[4 * EDIM * EDIM];
static __device__ __align__(16) unsigned short g_qh[NH * LL * HDIM];
static __device__ __align__(16) unsigned short g_ql[NH * LL * HDIM];
static __device__ __align__(16) unsigned short g_kh[NH * SSQ * HDIM];
static __device__ __align__(16) unsigned short g_kl[NH * SSQ * HDIM];
static __device__ __align__(16) unsigned short g_sch[(size_t)NH * LL * SSQ];
static __device__ __align__(16) unsigned short g_scl[(size_t)NH * LL * SSQ];
static __device__ __align__(16) unsigned short g_ctxh[RTOT * EDIM];
static __device__ __align__(16) unsigned short g_ctxl[RTOT * EDIM];

__device__ __forceinline__ void mma_bf16(float* d, const unsigned* a,
                                         unsigned b0, unsigned b1) {
    asm volatile(
        "mma.sync.aligned.m16n8k16.row.col.f32.bf16.bf16.f32 "
        "{%0,%1,%2,%3},{%4,%5,%6,%7},{%8,%9},{%0,%1,%2,%3};\n"
        : "+f"(d[0]), "+f"(d[1]), "+f"(d[2]), "+f"(d[3])
        : "r"(a[0]), "r"(a[1]), "r"(a[2]), "r"(a[3]), "r"(b0), "r"(b1));
}

__device__ __forceinline__ void split2(float x, float y,
                                       unsigned &hi, unsigned &lo) {
    unsigned h;
    asm("cvt.rn.bf16x2.f32 %0, %1, %2;" : "=r"(h) : "f"(y), "f"(x));
    __nv_bfloat162 hb = *reinterpret_cast<__nv_bfloat162*>(&h);
    float rx = x - __bfloat162float(hb.x);
    float ry = y - __bfloat162float(hb.y);
    unsigned l;
    asm("cvt.rn.bf16x2.f32 %0, %1, %2;" : "=r"(l) : "f"(ry), "f"(rx));
    hi = h; lo = l;
}

// ============================================================================
// K0a: decode mem_mask regardless of upload encoding.
__global__ __launch_bounds__(256) void mask_decode_kernel(
    const unsigned int* __restrict__ m)
{
    __shared__ int enc_flags;
    if (threadIdx.x == 0) enc_flags = 0;
    __syncthreads();
    for (int i = threadIdx.x; i < 512; i += 256) {
        unsigned int w = m[i];
        if ((w & 0xFFFFu) == 0x3F80u) atomicOr(&enc_flags, 2);
        else if ((w >> 8) != 0 && w != 0x3F800000u) atomicOr(&enc_flags, 1);
    }
    __syncthreads();
    int f = enc_flags;
    if (f & 2) {
        const unsigned short* mh = (const unsigned short*)m;
        for (int i = threadIdx.x; i < NBATCH * MMEM; i += 256)
            g_mask[i] = mh[i] ? 1 : 0;
    } else if (f & 1) {
        const unsigned char* mb = (const unsigned char*)m;
        for (int i = threadIdx.x; i < NBATCH * MMEM; i += 256)
            g_mask[i] = mb[i] ? 1 : 0;
    } else {
        for (int i = threadIdx.x; i < NBATCH * MMEM; i += 256)
            g_mask[i] = m[i] ? 1 : 0;
    }
}

// K0b: pre-split fp32 -> bf16 hi/lo planes.
__global__ __launch_bounds__(256) void split_kernel(
    const float* __restrict__ src, int dst_sel, size_t dst_off, int n2)
{
    unsigned* dh = (unsigned*)((dst_sel == 0 ? g_xh : g_wsh) + dst_off);
    unsigned* dl = (unsigned*)((dst_sel == 0 ? g_xl : g_wsl) + dst_off);
    for (int i = blockIdx.x * 256 + threadIdx.x; i < n2; i += gridDim.x * 256) {
        float2 v = ((const float2*)src)[i];
        unsigned hi, lo;
        split2(v.x, v.y, hi, lo);
        dh[i] = hi; dl[i] = lo;
    }
}

// K0c: g_sv[nh][d] = sum_s v[nh][s][d]
__global__ __launch_bounds__(256) void vsum_kernel()
{
    __shared__ float p[4][64];
    int nh = blockIdx.x, d = threadIdx.x & 63, sg = threadIdx.x >> 6;
    const float* V = g_v + (size_t)nh * SSQ * HDIM;
    float s = 0.f;
    for (int ss = sg; ss < SSQ; ss += 4) s += V[(size_t)ss * 64 + d];
    p[sg][d] = s;
    __syncthreads();
    if (threadIdx.x < 64)
        g_sv[nh * 64 + threadIdx.x] = p[0][threadIdx.x] + p[1][threadIdx.x] +
                                      p[2][threadIdx.x] + p[3][threadIdx.x];
}

// ============================================================================
// K1: unified projection GEMM, 3-pass split-bf16 mma.
// ============================================================================
__global__ __launch_bounds__(256, 1) void proj_mma(
    const float* __restrict__ Bi, const float* __restrict__ Bo,
    const float* __restrict__ rq, const float* __restrict__ rk,
    float* __restrict__ out, int base_mode)
{
    const int mode = base_mode + blockIdx.z;
    const unsigned* APh = (const unsigned*)(mode < 3 ?
        g_xh + (size_t)mode * RTOT * EDIM : g_ctxh);
    const unsigned* APl = (const unsigned*)(mode < 3 ?
        g_xl + (size_t)mode * RTOT * EDIM : g_ctxl);
    const unsigned* BPh = (const unsigned*)(g_wsh + (size_t)mode * EDIM * EDIM);
    const unsigned* BPl = (const unsigned*)(g_wsl + (size_t)mode * EDIM * EDIM);
    const float* Bm = (mode < 3) ? Bi + mode * EDIM : Bo;
    const float* rot = (mode == 0) ? rq : rk;

    __shared__ unsigned Ah[128][20], Al[128][20], Bh[128][20], Bl[128][20];

    const int t = threadIdx.x;
    const int warp = t >> 5, lane = t & 31;
    const int g = lane >> 2, tq = lane & 3;
    const int wm = warp >> 1, wn = warp & 1;
    const int row0 = blockIdx.y * 128, col0 = blockIdx.x * 128;
    const int sr = t >> 2, sc4 = (t & 3) * 4;

    float D[2][8][4] = {};
    uint4 rah[2], ral[2], rbh[2], rbl[2];

#pragma unroll
    for (int j = 0; j < 2; j++) {
        int r = sr + j * 64;
        size_t ao = (size_t)(row0 + r) * 256 + sc4;
        size_t bo = (size_t)(col0 + r) * 256 + sc4;
        rah[j] = *(const uint4*)(APh + ao);
        ral[j] = *(const uint4*)(APl + ao);
        rbh[j] = *(const uint4*)(BPh + bo);
        rbl[j] = *(const uint4*)(BPl + bo);
    }

    for (int kc = 0; kc < 16; kc++) {
        __syncthreads();
#pragma unroll
        for (int j = 0; j < 2; j++) {
            int r = sr + j * 64;
            *(uint4*)&Ah[r][sc4] = rah[j];
            *(uint4*)&Al[r][sc4] = ral[j];
            *(uint4*)&Bh[r][sc4] = rbh[j];
            *(uint4*)&Bl[r][sc4] = rbl[j];
        }
        __syncthreads();
        if (kc < 15) {
#pragma unroll
            for (int j = 0; j < 2; j++) {
                int r = sr + j * 64;
                size_t ao = (size_t)(row0 + r) * 256 + (kc + 1) * 16 + sc4;
                size_t bo = (size_t)(col0 + r) * 256 + (kc + 1) * 16 + sc4;
                rah[j] = *(const uint4*)(APh + ao);
                ral[j] = *(const uint4*)(APl + ao);
                rbh[j] = *(const uint4*)(BPh + bo);
                rbl[j] = *(const uint4*)(BPl + bo);
            }
        }
#pragma unroll
        for (int ks = 0; ks < 2; ks++) {
            unsigned ah[2][4], al_[2][4];
#pragma unroll
            for (int mt = 0; mt < 2; mt++) {
                int m = wm * 32 + mt * 16 + g;
                ah[mt][0]  = Ah[m][ks * 8 + tq];
                ah[mt][1]  = Ah[m + 8][ks * 8 + tq];
                ah[mt][2]  = Ah[m][ks * 8 + tq + 4];
                ah[mt][3]  = Ah[m + 8][ks * 8 + tq + 4];
                al_[mt][0] = Al[m][ks * 8 + tq];
                al_[mt][1] = Al[m + 8][ks * 8 + tq];
                al_[mt][2] = Al[m][ks * 8 + tq + 4];
                al_[mt][3] = Al[m + 8][ks * 8 + tq + 4];
            }
#pragma unroll
            for (int nt = 0; nt < 8; nt++) {
                int n = wn * 64 + nt * 8 + g;
                unsigned bh0 = Bh[n][ks * 8 + tq], bh1 = Bh[n][ks * 8 + tq + 4];
                unsigned bl0 = Bl[n][ks * 8 + tq], bl1 = Bl[n][ks * 8 + tq + 4];
#pragma unroll
                for (int mt = 0; mt < 2; mt++) {
                    mma_bf16(D[mt][nt], ah[mt], bh0, bh1);
                    mma_bf16(D[mt][nt], ah[mt], bl0, bl1);
                    mma_bf16(D[mt][nt], al_[mt], bh0, bh1);
                }
            }
        }
    }

    const float scale = (mode == 0) ? 0.125f : 1.0f;
#pragma unroll
    for (int mt = 0; mt < 2; mt++) {
#pragma unroll
        for (int half = 0; half < 2; half++) {
            int r = row0 + wm * 32 + mt * 16 + g + half * 8;
#pragma unroll
            for (int nt = 0; nt < 8; nt++) {
                int c = col0 + wn * 64 + nt * 8 + tq * 2;
                float v0 = D[mt][nt][half * 2 + 0] + Bm[c];
                float v1 = D[mt][nt][half * 2 + 1] + Bm[c + 1];
                if (mode == 3) {
                    *(float2*)(out + (size_t)r * EDIM + c) = make_float2(v0, v1);
                } else if (mode == 2) {
                    int l = r >> 3, nn = r & 7;
                    *(float2*)(g_v + (size_t)((nn * NHEAD + (c >> 6)) * LL + l)
                               * HDIM + (c & 63)) = make_float2(v0, v1);
                } else {
                    v0 *= scale; v1 *= scale;
                    int l = r >> 3, nn = r & 7;
                    const float* rp = rot + ((size_t)(nn * LL + l) * EDIM + c) * 2;
                    float4 rr = *(const float4*)rp;
                    float o0 = v0 * rr.x - v1 * rr.y;
                    float o1 = v1 * rr.z + v0 * rr.w;
                    size_t off = (size_t)((nn * NHEAD + (c >> 6)) * LL + l)
                                 * HDIM + (c & 63);
                    unsigned ph, pl;
                    split2(o0, o1, ph, pl);
                    if (mode == 0) {
                        ((unsigned*)g_qh)[off >> 1] = ph;
                        ((unsigned*)g_ql)[off >> 1] = pl;
                    } else {
                        ((unsigned*)g_kh)[off >> 1] = ph;
                        ((unsigned*)g_kl)[off >> 1] = pl;
                    }
                }
            }
        }
    }
}

// ============================================================================
// K2: exp(scores) via 3-pass split-bf16 mma; split-plane output + col partials.
// ============================================================================
__global__ __launch_bounds__(256, 1) void scores_mma()
{
    __shared__ unsigned X[128][36], Y[128][36];
    __shared__ float red[8][64];

    const int nh = blockIdx.z;
    const int l0 = blockIdx.y * 128, s0 = blockIdx.x * 128;
    const int t = threadIdx.x;
    const int warp = t >> 5, lane = t & 31;
    const int g = lane >> 2, tq = lane & 3;
    const int wm = warp >> 1, wn = warp & 1;

    const unsigned* QH = (const unsigned*)g_qh + ((size_t)nh * LL + l0) * 32;
    const unsigned* QL = (const unsigned*)g_ql + ((size_t)nh * LL + l0) * 32;
    const unsigned* KH = (const unsigned*)g_kh + ((size_t)nh * SSQ + s0) * 32;
    const unsigned* KL = (const unsigned*)g_kl + ((size_t)nh * SSQ + s0) * 32;

    float D[2][8][4] = {};

    auto stageP = [&](unsigned (*buf)[36], const unsigned* src) {
#pragma unroll
        for (int j = 0; j < 4; j++) {
            int idx = t + 256 * j, r = idx >> 3, q4 = idx & 7;
            *(uint4*)&buf[r][q4 * 4] = *(const uint4*)(src + (size_t)r * 32 + q4 * 4);
        }
    };
    auto do_pass = [&]() {
#pragma unroll
        for (int ks = 0; ks < 4; ks++) {
            unsigned a[2][4];
#pragma unroll
            for (int mt = 0; mt < 2; mt++) {
                int m = wm * 32 + mt * 16 + g;
                a[mt][0] = X[m][ks * 8 + tq];
                a[mt][1] = X[m + 8][ks * 8 + tq];
                a[mt][2] = X[m][ks * 8 + tq + 4];
                a[mt][3] = X[m + 8][ks * 8 + tq + 4];
            }
#pragma unroll
            for (int nt = 0; nt < 8; nt++) {
                int n = wn * 64 + nt * 8 + g;
                unsigned b0 = Y[n][ks * 8 + tq], b1 = Y[n][ks * 8 + tq + 4];
#pragma unroll
                for (int mt = 0; mt < 2; mt++)
                    mma_bf16(D[mt][nt], a[mt], b0, b1);
            }
        }
    };

    stageP(X, QH); stageP(Y, KH);
    __syncthreads(); do_pass();          // qh*kh
    __syncthreads(); stageP(X, QL);
    __syncthreads(); do_pass();          // ql*kh
    __syncthreads(); stageP(X, QH); stageP(Y, KL);
    __syncthreads(); do_pass();          // qh*kl

    unsigned* SCH = (unsigned*)g_sch + ((size_t)nh << 19);
    unsigned* SCL = (unsigned*)g_scl + ((size_t)nh << 19);
    float cs[8][2] = {};
#pragma unroll
    for (int mt = 0; mt < 2; mt++) {
#pragma unroll
        for (int half = 0; half < 2; half++) {
            int l = l0 + wm * 32 + mt * 16 + g + half * 8;
#pragma unroll
            for (int nt = 0; nt < 8; nt++) {
                int s = s0 + wn * 64 + nt * 8 + tq * 2;
                float e0 = __expf(D[mt][nt][half * 2 + 0]);
                float e1 = __expf(D[mt][nt][half * 2 + 1]);
                unsigned hi, lo;
                split2(e0, e1, hi, lo);
                size_t ui = (size_t)l * 512 + (s >> 1);
                SCH[ui] = hi; SCL[ui] = lo;
                cs[nt][0] += e0;
                cs[nt][1] += e1;
            }
        }
    }
#pragma unroll
    for (int nt = 0; nt < 8; nt++) {
#pragma unroll
        for (int c2 = 0; c2 < 2; c2++) {
            float v = cs[nt][c2];
            v += __shfl_xor_sync(0xffffffffu, v, 4);
            v += __shfl_xor_sync(0xffffffffu, v, 8);
            v += __shfl_xor_sync(0xffffffffu, v, 16);
            if (g == 0) red[warp][nt * 8 + tq * 2 + c2] = v;
        }
    }
    __syncthreads();
    if (t < 128) {
        int wnn = t >> 6, cc = t & 63;
        float tot = red[wnn][cc] + red[wnn + 2][cc] +
                    red[wnn + 4][cc] + red[wnn + 6][cc];
        g_cpart[((size_t)nh * 8 + blockIdx.y) * SSQ + s0 + t] = tot;
    }
}

// ============================================================================
// K3: reduce 8 column partials -> g_csum.
__global__ __launch_bounds__(256) void colsum2_kernel()
{
    int nh = blockIdx.y, s = blockIdx.x * 256 + threadIdx.x;
    float sum = 0.f;
#pragma unroll
    for (int j = 0; j < 8; j++)
        sum += g_cpart[((size_t)nh * 8 + j) * SSQ + s];
    g_csum[nh * SSQ + s] = sum;
}

// ============================================================================
// K4: main attention via 3-pass split-bf16 mma (unchanged from R13).
// ============================================================================
__global__ __launch_bounds__(256, 1) void attn_main_mma()
{
    __shared__ unsigned Wh[128][20], Wl[128][20];
    __shared__ unsigned Vth[64][18], Vtl[64][18];
    __shared__ float cinv[1024];
    __shared__ float rsp[128][4];
    __shared__ float rowinv[128];

    const int nh = blockIdx.y, l0 = blockIdx.x * 128;
    const int t = threadIdx.x;
    const int warp = t >> 5, lane = t & 31;
    const int g = lane >> 2, tq = lane & 3;
    const int wm = warp >> 1, wn = warp & 1;

    const unsigned* SH = (const unsigned*)g_sch + ((size_t)nh << 19);
    const unsigned* SL = (const unsigned*)g_scl + ((size_t)nh << 19);
    const float* V = g_v + (size_t)nh * SSQ * HDIM;

#pragma unroll
    for (int j = 0; j < 4; j++)
        cinv[t + 256 * j] = 1.f / g_csum[nh * SSQ + t + 256 * j];

    float D[2][4][4] = {};
    float rsum0 = 0.f, rsum1 = 0.f;

    const int wr = t >> 2, wq = t & 3;
    const int vs = t >> 3, vq = (t & 7) * 8;

    uint4 wh0, wl0, wh1, wl1;
    float4 va, vb;
    wh0 = *(const uint4*)(SH + (size_t)(l0 + wr) * 512 + wq * 4);
    wl0 = *(const uint4*)(SL + (size_t)(l0 + wr) * 512 + wq * 4);
    wh1 = *(const uint4*)(SH + (size_t)(l0 + 64 + wr) * 512 + wq * 4);
    wl1 = *(const uint4*)(SL + (size_t)(l0 + 64 + wr) * 512 + wq * 4);
    va = *(const float4*)(V + (size_t)vs * 64 + vq);
    vb = *(const float4*)(V + (size_t)vs * 64 + vq + 4);
    __syncthreads();

    for (int c = 0; c < 32; c++) {
        const int s0 = c * 32;
#pragma unroll
        for (int rr = 0; rr < 2; rr++) {
            uint4 H = rr ? wh1 : wh0, L = rr ? wl1 : wl0;
            int row = rr * 64 + wr;
            *(uint4*)&Wh[row][wq * 4] = H;
            *(uint4*)&Wl[row][wq * 4] = L;
            const unsigned* hp = (const unsigned*)&H;
            const unsigned* lp = (const unsigned*)&L;
            float rs = 0.f;
#pragma unroll
            for (int u = 0; u < 4; u++) {
                float2 h2 = __bfloat1622float2(*(const __nv_bfloat162*)&hp[u]);
                float2 l2 = __bfloat1622float2(*(const __nv_bfloat162*)&lp[u]);
                int s = s0 + wq * 8 + u * 2;
                rs += (h2.x + l2.x) * cinv[s] + (h2.y + l2.y) * cinv[s + 1];
            }
            if (rr == 0) rsum0 += rs; else rsum1 += rs;
        }
        {
            float cv = cinv[s0 + vs];
            float vv[8] = {va.x * cv, va.y * cv, va.z * cv, va.w * cv,
                           vb.x * cv, vb.y * cv, vb.z * cv, vb.w * cv};
            unsigned short* ph = (unsigned short*)Vth;
            unsigned short* pl = (unsigned short*)Vtl;
#pragma unroll
            for (int j = 0; j < 8; j++) {
                int d = vq + j;
                __nv_bfloat16 h = __float2bfloat16(vv[j]);
                __nv_bfloat16 l = __float2bfloat16(vv[j] - __bfloat162float(h));
                ph[d * 36 + vs] = __bfloat16_as_ushort(h);
                pl[d * 36 + vs] = __bfloat16_as_ushort(l);
            }
        }
        __syncthreads();
        if (c < 31) {
            int sn = s0 + 32;
            wh0 = *(const uint4*)(SH + (size_t)(l0 + wr) * 512 + sn / 2 + wq * 4);
            wl0 = *(const uint4*)(SL + (size_t)(l0 + wr) * 512 + sn / 2 + wq * 4);
            wh1 = *(const uint4*)(SH + (size_t)(l0 + 64 + wr) * 512 + sn / 2 + wq * 4);
            wl1 = *(const uint4*)(SL + (size_t)(l0 + 64 + wr) * 512 + sn / 2 + wq * 4);
            va = *(const float4*)(V + (size_t)(sn + vs) * 64 + vq);
            vb = *(const float4*)(V + (size_t)(sn + vs) * 64 + vq + 4);
        }
#pragma unroll
        for (int ks = 0; ks < 2; ks++) {
            unsigned ah[2][4], al_[2][4];
#pragma unroll
            for (int mt = 0; mt < 2; mt++) {
                int m = wm * 32 + mt * 16 + g;
                ah[mt][0]  = Wh[m][ks * 8 + tq];
                ah[mt][1]  = Wh[m + 8][ks * 8 + tq];
                ah[mt][2]  = Wh[m][ks * 8 + tq + 4];
                ah[mt][3]  = Wh[m + 8][ks * 8 + tq + 4];
                al_[mt][0] = Wl[m][ks * 8 + tq];
                al_[mt][1] = Wl[m + 8][ks * 8 + tq];
                al_[mt][2] = Wl[m][ks * 8 + tq + 4];
                al_[mt][3] = Wl[m + 8][ks * 8 + tq + 4];
            }
#pragma unroll
            for (int nt = 0; nt < 4; nt++) {
                int n = wn * 32 + nt * 8 + g;
                unsigned bh0 = Vth[n][ks * 8 + tq], bh1 = Vth[n][ks * 8 + tq + 4];
                unsigned bl0 = Vtl[n][ks * 8 + tq], bl1 = Vtl[n][ks * 8 + tq + 4];
#pragma unroll
                for (int mt = 0; mt < 2; mt++) {
                    mma_bf16(D[mt][nt], ah[mt], bh0, bh1);
                    mma_bf16(D[mt][nt], al_[mt], bh0, bh1);
                    mma_bf16(D[mt][nt], ah[mt], bl0, bl1);
                }
            }
        }
        __syncthreads();
    }

    rsp[wr][wq] = rsum0;
    rsp[64 + wr][wq] = rsum1;
    __syncthreads();
    if (t < 128)
        rowinv[t] = 1.f / (rsp[t][0] + rsp[t][1] + rsp[t][2] + rsp[t][3]
                           + 1.024e-5f);
    __syncthreads();

    float* dst = g_attn + (size_t)nh * LL * HDIM;
    const float* sv = g_sv + nh * 64;
#pragma unroll
    for (int mt = 0; mt < 2; mt++) {
#pragma unroll
        for (int half = 0; half < 2; half++) {
            int r = wm * 32 + mt * 16 + g + half * 8;
            float inv = rowinv[r];
#pragma unroll
            for (int nt = 0; nt < 4; nt++) {
                int d = wn * 32 + nt * 8 + tq * 2;
                *(float2*)(dst + (size_t)(l0 + r) * 64 + d) = make_float2(
                    (D[mt][nt][half * 2 + 0] + 1e-8f * sv[d]) * inv,
                    (D[mt][nt][half * 2 + 1] + 1e-8f * sv[d + 1]) * inv);
            }
        }
    }
}

// ============================================================================
// K5: memory branch via 3-pass split-bf16 mma (both GEMMs) + gate combine.
// l-tile 64; m-chunks of 32. P round-trips through smem as split bf16.
// ============================================================================
__global__ __launch_bounds__(256, 1) void attn_mem_mma(
    const float* __restrict__ kmem, const float* __restrict__ vmem,
    const float* __restrict__ gatew)
{
    __shared__ unsigned Qh[64][36], Ql[64][36];
    __shared__ unsigned Kh[32][36], Kl[32][36];
    __shared__ unsigned Ph[64][18], Pl[64][18];
    __shared__ unsigned Vth[64][18], Vtl[64][18];
    __shared__ float mask_s[256];
    __shared__ float rs[64][2];

    const int nh = blockIdx.y;
    const int n = nh >> 3, h = nh & 7;
    const int l0 = blockIdx.x * 64;
    const int t = threadIdx.x;
    const int lane = t & 31, warp = t >> 5;
    const int g = lane >> 2, tq = lane & 3;
    const int wm = warp >> 1, wn = warp & 1;

    // stage Q planes (pure copies): 64 rows x 32 unsigned
    {
        int r = t >> 2, c = (t & 3) * 8;
        const unsigned* qh = (const unsigned*)g_qh + ((size_t)nh * LL + l0 + r) * 32;
        const unsigned* ql = (const unsigned*)g_ql + ((size_t)nh * LL + l0 + r) * 32;
        *(uint4*)&Qh[r][c]     = *(const uint4*)(qh + c);
        *(uint4*)&Qh[r][c + 4] = *(const uint4*)(qh + c + 4);
        *(uint4*)&Ql[r][c]     = *(const uint4*)(ql + c);
        *(uint4*)&Ql[r][c + 4] = *(const uint4*)(ql + c + 4);
    }
    mask_s[t] = g_mask[n * MMEM + t] ? 1.f : 0.f;

    float D2[4][4] = {};
    float rsA[2] = {0.f, 0.f};

    const int mr = t >> 3, kq = (t & 7) * 8;   // K/V chunk loader

    for (int m0 = 0; m0 < MMEM; m0 += 32) {
        const float* kp = kmem + ((size_t)(m0 + mr) * NBATCH + n) * EDIM + h * 64 + kq;
        const float* vp = vmem + ((size_t)(m0 + mr) * NBATCH + n) * EDIM + h * 64 + kq;
        float4 k0 = *(const float4*)(kp);
        float4 k1 = *(const float4*)(kp + 4);
        float4 v0 = *(const float4*)(vp);
        float4 v1 = *(const float4*)(vp + 4);
        __syncthreads();   // prior chunk's GEMMs done with Kh/Vt/Ph
        {
            unsigned h0, lo0, h1, lo1, h2, lo2, h3, lo3;
            split2(k0.x, k0.y, h0, lo0); split2(k0.z, k0.w, h1, lo1);
            split2(k1.x, k1.y, h2, lo2); split2(k1.z, k1.w, h3, lo3);
            *(uint4*)&Kh[mr][(t & 7) * 4] = make_uint4(h0, h1, h2, h3);
            *(uint4*)&Kl[mr][(t & 7) * 4] = make_uint4(lo0, lo1, lo2, lo3);
            float vv[8] = {v0.x, v0.y, v0.z, v0.w, v1.x, v1.y, v1.z, v1.w};
            unsigned short* ph = (unsigned short*)Vth;
            unsigned short* pl = (unsigned short*)Vtl;
#pragma unroll
            for (int j = 0; j < 8; j++) {
                int d = kq + j;
                __nv_bfloat16 hh = __float2bfloat16(vv[j]);
                __nv_bfloat16 ll = __float2bfloat16(vv[j] - __bfloat162float(hh));
                ph[d * 36 + mr] = __bfloat16_as_ushort(hh);
                pl[d * 36 + mr] = __bfloat16_as_ushort(ll);
            }
        }
        __syncthreads();

        // GEMM1: sm[64 l][32 m], 3-pass split-bf16
        float D1[2][4] = {};
#pragma unroll
        for (int ks = 0; ks < 4; ks++) {
            unsigned ah[4], al_[4];
            int m = wm * 16 + g;
            ah[0]  = Qh[m][ks * 8 + tq];
            ah[1]  = Qh[m + 8][ks * 8 + tq];
            ah[2]  = Qh[m][ks * 8 + tq + 4];
            ah[3]  = Qh[m + 8][ks * 8 + tq + 4];
            al_[0] = Ql[m][ks * 8 + tq];
            al_[1] = Ql[m + 8][ks * 8 + tq];
            al_[2] = Ql[m][ks * 8 + tq + 4];
            al_[3] = Ql[m + 8][ks * 8 + tq + 4];
#pragma unroll
            for (int nt = 0; nt < 2; nt++) {
                int nn = wn * 16 + nt * 8 + g;
                unsigned bh0 = Kh[nn][ks * 8 + tq], bh1 = Kh[nn][ks * 8 + tq + 4];
                unsigned bl0 = Kl[nn][ks * 8 + tq], bl1 = Kl[nn][ks * 8 + tq + 4];
                mma_bf16(D1[nt], ah,  bh0, bh1);
                mma_bf16(D1[nt], al_, bh0, bh1);
                mma_bf16(D1[nt], ah,  bl0, bl1);
            }
        }
        // epilogue: mask + exp, split P to smem, accumulate rowsums
#pragma unroll
        for (int nt = 0; nt < 2; nt++) {
            int mcol = wn * 16 + nt * 8 + tq * 2;
            float msk0 = mask_s[m0 + mcol];
            float msk1 = mask_s[m0 + mcol + 1];
#pragma unroll
            for (int half = 0; half < 2; half++) {
                float p0 = (msk0 != 0.f) ? 0.f : __expf(D1[nt][half * 2 + 0]);
                float p1 = (msk1 != 0.f) ? 0.f : __expf(D1[nt][half * 2 + 1]);
                rsA[half] += p0 + p1;
                int row = wm * 16 + g + half * 8;
                unsigned hi, lo;
                split2(p0, p1, hi, lo);
                Ph[row][wn * 8 + nt * 4 + tq] = hi;
                Pl[row][wn * 8 + nt * 4 + tq] = lo;
            }
        }
        __syncthreads();

        // GEMM2: O[64 l][64 d] += P @ Vt, 3-pass split-bf16, k=32
#pragma unroll
        for (int ks = 0; ks < 2; ks++) {
            unsigned ah[4], al_[4];
            int m = wm * 16 + g;
            ah[0]  = Ph[m][ks * 8 + tq];
            ah[1]  = Ph[m + 8][ks * 8 + tq];
            ah[2]  = Ph[m][ks * 8 + tq + 4];
            ah[3]  = Ph[m + 8][ks * 8 + tq + 4];
            al_[0] = Pl[m][ks * 8 + tq];
            al_[1] = Pl[m + 8][ks * 8 + tq];
            al_[2] = Pl[m][ks * 8 + tq + 4];
            al_[3] = Pl[m + 8][ks * 8 + tq + 4];
#pragma unroll
            for (int nt = 0; nt < 4; nt++) {
                int nn = wn * 32 + nt * 8 + g;
                unsigned bh0 = Vth[nn][ks * 8 + tq], bh1 = Vth[nn][ks * 8 + tq + 4];
                unsigned bl0 = Vtl[nn][ks * 8 + tq], bl1 = Vtl[nn][ks * 8 + tq + 4];
                mma_bf16(D2[nt], ah,  bh0, bh1);
                mma_bf16(D2[nt], al_, bh0, bh1);
                mma_bf16(D2[nt], ah,  bl0, bl1);
            }
        }
    }

    // rowsum: reduce over tq group, then across wn via smem
    float r0 = rsA[0], r1 = rsA[1];
    r0 += __shfl_xor_sync(0xffffffffu, r0, 1);
    r0 += __shfl_xor_sync(0xffffffffu, r0, 2);
    r1 += __shfl_xor_sync(0xffffffffu, r1, 1);
    r1 += __shfl_xor_sync(0xffffffffu, r1, 2);
    __syncthreads();   // GEMM2 done reading Ph before rs reuse is fine (rs separate)
    if (tq == 0) {
        rs[wm * 16 + g][wn]     = r0;
        rs[wm * 16 + g + 8][wn] = r1;
    }
    __syncthreads();

    const float gate = 1.f / (1.f + __expf(-gatew[h]));
    const float omg = 1.f - gate;
#pragma unroll
    for (int half = 0; half < 2; half++) {
        int rl = wm * 16 + g + half * 8;
        int l = l0 + rl;
        float inv = 1.f / (rs[rl][0] + rs[rl][1]);
#pragma unroll
        for (int nt = 0; nt < 4; nt++) {
            int d = wn * 32 + nt * 8 + tq * 2;
            float2 am = *(const float2*)(g_attn + ((size_t)nh * LL + l) * 64 + d);
            float o0 = gate * (D2[nt][half * 2 + 0] * inv) + omg * am.x;
            float o1 = gate * (D2[nt][half * 2 + 1] * inv) + omg * am.y;
            unsigned hi, lo;
            split2(o0, o1, hi, lo);
            size_t ui = (((size_t)l * NBATCH + n) * EDIM + h * 64 + d) >> 1;
            ((unsigned*)g_ctxh)[ui] = hi;
            ((unsigned*)g_ctxl)[ui] = lo;
        }
    }
}

// ============================================================================
extern "C" void kernel_launch(void* const* d_in, const int* in_sizes, int n_in,
                              void* d_out, int out_size)
{
    const float* query = (const float*)d_in[0];
    const float* key   = (const float*)d_in[1];
    const float* value = (const float*)d_in[2];
    const float* Wi    = (const float*)d_in[3];
    const float* Bi    = (const float*)d_in[4];
    const float* Wo    = (const float*)d_in[5];
    const float* Bo    = (const float*)d_in[6];
    const float* rq    = (const float*)d_in[7];
    const float* rk    = (const float*)d_in[8];
    const float* kmem  = (const float*)d_in[9];
    const float* vmem  = (const float*)d_in[10];
    const float* gate  = (const float*)d_in[11];
    const unsigned int* mmask_raw = (const unsigned int*)d_in[12];
    float* out = (float*)d_out;

    const int NX2 = RTOT * EDIM / 2;
    const int NW2 = 3 * EDIM * EDIM / 2;
    const int NWO2 = EDIM * EDIM / 2;

    mask_decode_kernel<<<1, 256>>>(mmask_raw);
    split_kernel<<<2048, 256>>>(query, 0, 0, NX2);
    split_kernel<<<2048, 256>>>(key,   0, (size_t)RTOT * EDIM, NX2);
    split_kernel<<<2048, 256>>>(value, 0, (size_t)2 * RTOT * EDIM, NX2);
    split_kernel<<<1024, 256>>>(Wi, 1, 0, NW2);
    split_kernel<<<512, 256>>>(Wo, 1, (size_t)3 * EDIM * EDIM, NWO2);

    proj_mma<<<dim3(4, 64, 3), 256>>>(Bi, Bo, rq, rk, out, 0);
    vsum_kernel<<<64, 256>>>();
    scores_mma<<<dim3(8, 8, 64), 256>>>();
    colsum2_kernel<<<dim3(4, 64), 256>>>();
    attn_main_mma<<<dim3(8, 64), 256>>>();
    attn_mem_mma<<<dim3(16, 64), 256>>>(kmem, vmem, gate);
    proj_mma<<<dim3(4, 64, 1), 256>>>(Bi, Bo, rq, rk, out, 3);
}

// round 16
// speedup vs baseline: 1.8384x; 1.2382x over previous
#include <cuda_runtime.h>
#include <cuda_bf16.h>
#include <cuda_fp16.h>

#define LL     1024
#define SSQ    1024
#define MMEM   256
#define NBATCH 8
#define EDIM   512
#define NHEAD  8
#define HDIM   64
#define NH     64
#define RTOT   8192

// fp32 state
static __device__ __align__(16) float g_v[NH * SSQ * HDIM];
static __device__ __align__(16) float g_cpart[NH * 8 * SSQ];
static __device__ __align__(16) float g_csum[NH * SSQ];
static __device__ __align__(16) float g_attn[NH * LL * HDIM];
static __device__ __align__(16) float g_sv[NH * HDIM];
static __device__ unsigned char g_mask[NBATCH * MMEM];
// split bf16 planes (proj inputs/weights, scores, ctx)
static __device__ __align__(16) unsigned short g_xh[3 * RTOT * EDIM];
static __device__ __align__(16) unsigned short g_xl[3 * RTOT * EDIM];
static __device__ __align__(16) unsigned short g_wsh[4 * EDIM * EDIM];
static __device__ __align__(16) unsigned short g_wsl[4 * EDIM * EDIM];
static __device__ __align__(16) unsigned short g_sch[(size_t)NH * LL * SSQ];
static __device__ __align__(16) unsigned short g_scl[(size_t)NH * LL * SSQ];
static __device__ __align__(16) unsigned short g_ctxh[RTOT * EDIM];
static __device__ __align__(16) unsigned short g_ctxl[RTOT * EDIM];
// single fp16 planes (q, k)
static __device__ __align__(16) unsigned short g_qf[NH * LL * HDIM];
static __device__ __align__(16) unsigned short g_kf[NH * SSQ * HDIM];

__device__ __forceinline__ void mma_bf16(float* d, const unsigned* a,
                                         unsigned b0, unsigned b1) {
    asm volatile(
        "mma.sync.aligned.m16n8k16.row.col.f32.bf16.bf16.f32 "
        "{%0,%1,%2,%3},{%4,%5,%6,%7},{%8,%9},{%0,%1,%2,%3};\n"
        : "+f"(d[0]), "+f"(d[1]), "+f"(d[2]), "+f"(d[3])
        : "r"(a[0]), "r"(a[1]), "r"(a[2]), "r"(a[3]), "r"(b0), "r"(b1));
}

__device__ __forceinline__ void mma_f16(float* d, const unsigned* a,
                                        unsigned b0, unsigned b1) {
    asm volatile(
        "mma.sync.aligned.m16n8k16.row.col.f32.f16.f16.f32 "
        "{%0,%1,%2,%3},{%4,%5,%6,%7},{%8,%9},{%0,%1,%2,%3};\n"
        : "+f"(d[0]), "+f"(d[1]), "+f"(d[2]), "+f"(d[3])
        : "r"(a[0]), "r"(a[1]), "r"(a[2]), "r"(a[3]), "r"(b0), "r"(b1));
}

__device__ __forceinline__ void split2(float x, float y,
                                       unsigned &hi, unsigned &lo) {
    unsigned h;
    asm("cvt.rn.bf16x2.f32 %0, %1, %2;" : "=r"(h) : "f"(y), "f"(x));
    __nv_bfloat162 hb = *reinterpret_cast<__nv_bfloat162*>(&h);
    float rx = x - __bfloat162float(hb.x);
    float ry = y - __bfloat162float(hb.y);
    unsigned l;
    asm("cvt.rn.bf16x2.f32 %0, %1, %2;" : "=r"(l) : "f"(ry), "f"(rx));
    hi = h; lo = l;
}

__device__ __forceinline__ unsigned pack_f16(float x, float y) {
    unsigned r;
    asm("cvt.rn.f16x2.f32 %0, %1, %2;" : "=r"(r) : "f"(y), "f"(x));
    return r;
}

// ============================================================================
// K0a: decode mem_mask regardless of upload encoding.
__global__ __launch_bounds__(256) void mask_decode_kernel(
    const unsigned int* __restrict__ m)
{
    __shared__ int enc_flags;
    if (threadIdx.x == 0) enc_flags = 0;
    __syncthreads();
    for (int i = threadIdx.x; i < 512; i += 256) {
        unsigned int w = m[i];
        if ((w & 0xFFFFu) == 0x3F80u) atomicOr(&enc_flags, 2);
        else if ((w >> 8) != 0 && w != 0x3F800000u) atomicOr(&enc_flags, 1);
    }
    __syncthreads();
    int f = enc_flags;
    if (f & 2) {
        const unsigned short* mh = (const unsigned short*)m;
        for (int i = threadIdx.x; i < NBATCH * MMEM; i += 256)
            g_mask[i] = mh[i] ? 1 : 0;
    } else if (f & 1) {
        const unsigned char* mb = (const unsigned char*)m;
        for (int i = threadIdx.x; i < NBATCH * MMEM; i += 256)
            g_mask[i] = mb[i] ? 1 : 0;
    } else {
        for (int i = threadIdx.x; i < NBATCH * MMEM; i += 256)
            g_mask[i] = m[i] ? 1 : 0;
    }
}

// K0b: pre-split fp32 -> bf16 hi/lo planes.
__global__ __launch_bounds__(256) void split_kernel(
    const float* __restrict__ src, int dst_sel, size_t dst_off, int n2)
{
    unsigned* dh = (unsigned*)((dst_sel == 0 ? g_xh : g_wsh) + dst_off);
    unsigned* dl = (unsigned*)((dst_sel == 0 ? g_xl : g_wsl) + dst_off);
    for (int i = blockIdx.x * 256 + threadIdx.x; i < n2; i += gridDim.x * 256) {
        float2 v = ((const float2*)src)[i];
        unsigned hi, lo;
        split2(v.x, v.y, hi, lo);
        dh[i] = hi; dl[i] = lo;
    }
}

// K0c: g_sv[nh][d] = sum_s v[nh][s][d]
__global__ __launch_bounds__(256) void vsum_kernel()
{
    __shared__ float p[4][64];
    int nh = blockIdx.x, d = threadIdx.x & 63, sg = threadIdx.x >> 6;
    const float* V = g_v + (size_t)nh * SSQ * HDIM;
    float s = 0.f;
    for (int ss = sg; ss < SSQ; ss += 4) s += V[(size_t)ss * 64 + d];
    p[sg][d] = s;
    __syncthreads();
    if (threadIdx.x < 64)
        g_sv[nh * 64 + threadIdx.x] = p[0][threadIdx.x] + p[1][threadIdx.x] +
                                      p[2][threadIdx.x] + p[3][threadIdx.x];
}

// ============================================================================
// K1: unified projection GEMM, 3-pass split-bf16 mma (precision-critical).
// q/k epilogue now emits single fp16 planes.
// ============================================================================
__global__ __launch_bounds__(256, 1) void proj_mma(
    const float* __restrict__ Bi, const float* __restrict__ Bo,
    const float* __restrict__ rq, const float* __restrict__ rk,
    float* __restrict__ out, int base_mode)
{
    const int mode = base_mode + blockIdx.z;
    const unsigned* APh = (const unsigned*)(mode < 3 ?
        g_xh + (size_t)mode * RTOT * EDIM : g_ctxh);
    const unsigned* APl = (const unsigned*)(mode < 3 ?
        g_xl + (size_t)mode * RTOT * EDIM : g_ctxl);
    const unsigned* BPh = (const unsigned*)(g_wsh + (size_t)mode * EDIM * EDIM);
    const unsigned* BPl = (const unsigned*)(g_wsl + (size_t)mode * EDIM * EDIM);
    const float* Bm = (mode < 3) ? Bi + mode * EDIM : Bo;
    const float* rot = (mode == 0) ? rq : rk;

    __shared__ unsigned Ah[128][20], Al[128][20], Bh[128][20], Bl[128][20];

    const int t = threadIdx.x;
    const int warp = t >> 5, lane = t & 31;
    const int g = lane >> 2, tq = lane & 3;
    const int wm = warp >> 1, wn = warp & 1;
    const int row0 = blockIdx.y * 128, col0 = blockIdx.x * 128;
    const int sr = t >> 2, sc4 = (t & 3) * 4;

    float D[2][8][4] = {};
    uint4 rah[2], ral[2], rbh[2], rbl[2];

#pragma unroll
    for (int j = 0; j < 2; j++) {
        int r = sr + j * 64;
        size_t ao = (size_t)(row0 + r) * 256 + sc4;
        size_t bo = (size_t)(col0 + r) * 256 + sc4;
        rah[j] = *(const uint4*)(APh + ao);
        ral[j] = *(const uint4*)(APl + ao);
        rbh[j] = *(const uint4*)(BPh + bo);
        rbl[j] = *(const uint4*)(BPl + bo);
    }

    for (int kc = 0; kc < 16; kc++) {
        __syncthreads();
#pragma unroll
        for (int j = 0; j < 2; j++) {
            int r = sr + j * 64;
            *(uint4*)&Ah[r][sc4] = rah[j];
            *(uint4*)&Al[r][sc4] = ral[j];
            *(uint4*)&Bh[r][sc4] = rbh[j];
            *(uint4*)&Bl[r][sc4] = rbl[j];
        }
        __syncthreads();
        if (kc < 15) {
#pragma unroll
            for (int j = 0; j < 2; j++) {
                int r = sr + j * 64;
                size_t ao = (size_t)(row0 + r) * 256 + (kc + 1) * 16 + sc4;
                size_t bo = (size_t)(col0 + r) * 256 + (kc + 1) * 16 + sc4;
                rah[j] = *(const uint4*)(APh + ao);
                ral[j] = *(const uint4*)(APl + ao);
                rbh[j] = *(const uint4*)(BPh + bo);
                rbl[j] = *(const uint4*)(BPl + bo);
            }
        }
#pragma unroll
        for (int ks = 0; ks < 2; ks++) {
            unsigned ah[2][4], al_[2][4];
#pragma unroll
            for (int mt = 0; mt < 2; mt++) {
                int m = wm * 32 + mt * 16 + g;
                ah[mt][0]  = Ah[m][ks * 8 + tq];
                ah[mt][1]  = Ah[m + 8][ks * 8 + tq];
                ah[mt][2]  = Ah[m][ks * 8 + tq + 4];
                ah[mt][3]  = Ah[m + 8][ks * 8 + tq + 4];
                al_[mt][0] = Al[m][ks * 8 + tq];
                al_[mt][1] = Al[m + 8][ks * 8 + tq];
                al_[mt][2] = Al[m][ks * 8 + tq + 4];
                al_[mt][3] = Al[m + 8][ks * 8 + tq + 4];
            }
#pragma unroll
            for (int nt = 0; nt < 8; nt++) {
                int n = wn * 64 + nt * 8 + g;
                unsigned bh0 = Bh[n][ks * 8 + tq], bh1 = Bh[n][ks * 8 + tq + 4];
                unsigned bl0 = Bl[n][ks * 8 + tq], bl1 = Bl[n][ks * 8 + tq + 4];
#pragma unroll
                for (int mt = 0; mt < 2; mt++) {
                    mma_bf16(D[mt][nt], ah[mt], bh0, bh1);
                    mma_bf16(D[mt][nt], ah[mt], bl0, bl1);
                    mma_bf16(D[mt][nt], al_[mt], bh0, bh1);
                }
            }
        }
    }

    const float scale = (mode == 0) ? 0.125f : 1.0f;
#pragma unroll
    for (int mt = 0; mt < 2; mt++) {
#pragma unroll
        for (int half = 0; half < 2; half++) {
            int r = row0 + wm * 32 + mt * 16 + g + half * 8;
#pragma unroll
            for (int nt = 0; nt < 8; nt++) {
                int c = col0 + wn * 64 + nt * 8 + tq * 2;
                float v0 = D[mt][nt][half * 2 + 0] + Bm[c];
                float v1 = D[mt][nt][half * 2 + 1] + Bm[c + 1];
                if (mode == 3) {
                    *(float2*)(out + (size_t)r * EDIM + c) = make_float2(v0, v1);
                } else if (mode == 2) {
                    int l = r >> 3, nn = r & 7;
                    *(float2*)(g_v + (size_t)((nn * NHEAD + (c >> 6)) * LL + l)
                               * HDIM + (c & 63)) = make_float2(v0, v1);
                } else {
                    v0 *= scale; v1 *= scale;
                    int l = r >> 3, nn = r & 7;
                    const float* rp = rot + ((size_t)(nn * LL + l) * EDIM + c) * 2;
                    float4 rr = *(const float4*)rp;
                    float o0 = v0 * rr.x - v1 * rr.y;
                    float o1 = v1 * rr.z + v0 * rr.w;
                    size_t off = (size_t)((nn * NHEAD + (c >> 6)) * LL + l)
                                 * HDIM + (c & 63);
                    unsigned pf = pack_f16(o0, o1);
                    if (mode == 0) ((unsigned*)g_qf)[off >> 1] = pf;
                    else           ((unsigned*)g_kf)[off >> 1] = pf;
                }
            }
        }
    }
}

// ============================================================================
// K2: exp(scores) via SINGLE-pass fp16 mma; split-bf16 output + col partials.
// ============================================================================
__global__ __launch_bounds__(256, 1) void scores_mma()
{
    __shared__ unsigned X[128][36], Y[128][36];
    __shared__ float red[8][64];

    const int nh = blockIdx.z;
    const int l0 = blockIdx.y * 128, s0 = blockIdx.x * 128;
    const int t = threadIdx.x;
    const int warp = t >> 5, lane = t & 31;
    const int g = lane >> 2, tq = lane & 3;
    const int wm = warp >> 1, wn = warp & 1;

    const unsigned* QF = (const unsigned*)g_qf + ((size_t)nh * LL + l0) * 32;
    const unsigned* KF = (const unsigned*)g_kf + ((size_t)nh * SSQ + s0) * 32;

    float D[2][8][4] = {};

#pragma unroll
    for (int j = 0; j < 4; j++) {
        int idx = t + 256 * j, r = idx >> 3, q4 = idx & 7;
        *(uint4*)&X[r][q4 * 4] = *(const uint4*)(QF + (size_t)r * 32 + q4 * 4);
        *(uint4*)&Y[r][q4 * 4] = *(const uint4*)(KF + (size_t)r * 32 + q4 * 4);
    }
    __syncthreads();

#pragma unroll
    for (int ks = 0; ks < 4; ks++) {
        unsigned a[2][4];
#pragma unroll
        for (int mt = 0; mt < 2; mt++) {
            int m = wm * 32 + mt * 16 + g;
            a[mt][0] = X[m][ks * 8 + tq];
            a[mt][1] = X[m + 8][ks * 8 + tq];
            a[mt][2] = X[m][ks * 8 + tq + 4];
            a[mt][3] = X[m + 8][ks * 8 + tq + 4];
        }
#pragma unroll
        for (int nt = 0; nt < 8; nt++) {
            int n = wn * 64 + nt * 8 + g;
            unsigned b0 = Y[n][ks * 8 + tq], b1 = Y[n][ks * 8 + tq + 4];
#pragma unroll
            for (int mt = 0; mt < 2; mt++)
                mma_f16(D[mt][nt], a[mt], b0, b1);
        }
    }

    unsigned* SCH = (unsigned*)g_sch + ((size_t)nh << 19);
    unsigned* SCL = (unsigned*)g_scl + ((size_t)nh << 19);
    float cs[8][2] = {};
#pragma unroll
    for (int mt = 0; mt < 2; mt++) {
#pragma unroll
        for (int half = 0; half < 2; half++) {
            int l = l0 + wm * 32 + mt * 16 + g + half * 8;
#pragma unroll
            for (int nt = 0; nt < 8; nt++) {
                int s = s0 + wn * 64 + nt * 8 + tq * 2;
                float e0 = __expf(D[mt][nt][half * 2 + 0]);
                float e1 = __expf(D[mt][nt][half * 2 + 1]);
                unsigned hi, lo;
                split2(e0, e1, hi, lo);
                size_t ui = (size_t)l * 512 + (s >> 1);
                SCH[ui] = hi; SCL[ui] = lo;
                cs[nt][0] += e0;
                cs[nt][1] += e1;
            }
        }
    }
#pragma unroll
    for (int nt = 0; nt < 8; nt++) {
#pragma unroll
        for (int c2 = 0; c2 < 2; c2++) {
            float v = cs[nt][c2];
            v += __shfl_xor_sync(0xffffffffu, v, 4);
            v += __shfl_xor_sync(0xffffffffu, v, 8);
            v += __shfl_xor_sync(0xffffffffu, v, 16);
            if (g == 0) red[warp][nt * 8 + tq * 2 + c2] = v;
        }
    }
    __syncthreads();
    if (t < 128) {
        int wnn = t >> 6, cc = t & 63;
        float tot = red[wnn][cc] + red[wnn + 2][cc] +
                    red[wnn + 4][cc] + red[wnn + 6][cc];
        g_cpart[((size_t)nh * 8 + blockIdx.y) * SSQ + s0 + t] = tot;
    }
}

// ============================================================================
// K3: reduce 8 column partials -> g_csum.
__global__ __launch_bounds__(256) void colsum2_kernel()
{
    int nh = blockIdx.y, s = blockIdx.x * 256 + threadIdx.x;
    float sum = 0.f;
#pragma unroll
    for (int j = 0; j < 8; j++)
        sum += g_cpart[((size_t)nh * 8 + j) * SSQ + s];
    g_csum[nh * SSQ + s] = sum;
}

// ============================================================================
// K4: main attention SINGLE-pass fp16: w = (sch+scl)*cinv -> fp16 (in (0,1]),
// V raw fp16. attn = (w @ V + 1e-8*sv) / (rowsum + 1.024e-5).
// ============================================================================
__global__ __launch_bounds__(256, 1) void attn_main_mma()
{
    __shared__ unsigned Wf[128][20];
    __shared__ unsigned Vt[64][18];
    __shared__ float cinv[1024];
    __shared__ float rsp[128][4];
    __shared__ float rowinv[128];

    const int nh = blockIdx.y, l0 = blockIdx.x * 128;
    const int t = threadIdx.x;
    const int warp = t >> 5, lane = t & 31;
    const int g = lane >> 2, tq = lane & 3;
    const int wm = warp >> 1, wn = warp & 1;

    const unsigned* SH = (const unsigned*)g_sch + ((size_t)nh << 19);
    const unsigned* SL = (const unsigned*)g_scl + ((size_t)nh << 19);
    const float* V = g_v + (size_t)nh * SSQ * HDIM;

#pragma unroll
    for (int j = 0; j < 4; j++)
        cinv[t + 256 * j] = 1.f / g_csum[nh * SSQ + t + 256 * j];

    float D[2][4][4] = {};
    float rsum0 = 0.f, rsum1 = 0.f;

    const int wr = t >> 2, wq = t & 3;
    const int vs = t >> 3, vq = (t & 7) * 8;

    uint4 wh0, wl0, wh1, wl1;
    float4 va, vb;
    wh0 = *(const uint4*)(SH + (size_t)(l0 + wr) * 512 + wq * 4);
    wl0 = *(const uint4*)(SL + (size_t)(l0 + wr) * 512 + wq * 4);
    wh1 = *(const uint4*)(SH + (size_t)(l0 + 64 + wr) * 512 + wq * 4);
    wl1 = *(const uint4*)(SL + (size_t)(l0 + 64 + wr) * 512 + wq * 4);
    va = *(const float4*)(V + (size_t)vs * 64 + vq);
    vb = *(const float4*)(V + (size_t)vs * 64 + vq + 4);
    __syncthreads();

    for (int c = 0; c < 32; c++) {
        const int s0 = c * 32;
#pragma unroll
        for (int rr = 0; rr < 2; rr++) {
            uint4 H = rr ? wh1 : wh0, L = rr ? wl1 : wl0;
            int row = rr * 64 + wr;
            const unsigned* hp = (const unsigned*)&H;
            const unsigned* lp = (const unsigned*)&L;
            unsigned o4[4];
            float rs = 0.f;
#pragma unroll
            for (int u = 0; u < 4; u++) {
                float2 h2 = __bfloat1622float2(*(const __nv_bfloat162*)&hp[u]);
                float2 l2 = __bfloat1622float2(*(const __nv_bfloat162*)&lp[u]);
                int s = s0 + wq * 8 + u * 2;
                float w0 = (h2.x + l2.x) * cinv[s];
                float w1 = (h2.y + l2.y) * cinv[s + 1];
                rs += w0 + w1;
                o4[u] = pack_f16(w0, w1);
            }
            *(uint4*)&Wf[row][wq * 4] = make_uint4(o4[0], o4[1], o4[2], o4[3]);
            if (rr == 0) rsum0 += rs; else rsum1 += rs;
        }
        {
            float vv[8] = {va.x, va.y, va.z, va.w, vb.x, vb.y, vb.z, vb.w};
            unsigned short* pv = (unsigned short*)Vt;
#pragma unroll
            for (int j = 0; j < 8; j++)
                pv[(vq + j) * 36 + vs] =
                    __half_as_ushort(__float2half_rn(vv[j]));
        }
        __syncthreads();
        if (c < 31) {
            int sn = s0 + 32;
            wh0 = *(const uint4*)(SH + (size_t)(l0 + wr) * 512 + sn / 2 + wq * 4);
            wl0 = *(const uint4*)(SL + (size_t)(l0 + wr) * 512 + sn / 2 + wq * 4);
            wh1 = *(const uint4*)(SH + (size_t)(l0 + 64 + wr) * 512 + sn / 2 + wq * 4);
            wl1 = *(const uint4*)(SL + (size_t)(l0 + 64 + wr) * 512 + sn / 2 + wq * 4);
            va = *(const float4*)(V + (size_t)(sn + vs) * 64 + vq);
            vb = *(const float4*)(V + (size_t)(sn + vs) * 64 + vq + 4);
        }
#pragma unroll
        for (int ks = 0; ks < 2; ks++) {
            unsigned a[2][4];
#pragma unroll
            for (int mt = 0; mt < 2; mt++) {
                int m = wm * 32 + mt * 16 + g;
                a[mt][0] = Wf[m][ks * 8 + tq];
                a[mt][1] = Wf[m + 8][ks * 8 + tq];
                a[mt][2] = Wf[m][ks * 8 + tq + 4];
                a[mt][3] = Wf[m + 8][ks * 8 + tq + 4];
            }
#pragma unroll
            for (int nt = 0; nt < 4; nt++) {
                int n = wn * 32 + nt * 8 + g;
                unsigned b0 = Vt[n][ks * 8 + tq], b1 = Vt[n][ks * 8 + tq + 4];
#pragma unroll
                for (int mt = 0; mt < 2; mt++)
                    mma_f16(D[mt][nt], a[mt], b0, b1);
            }
        }
        __syncthreads();
    }

    rsp[wr][wq] = rsum0;
    rsp[64 + wr][wq] = rsum1;
    __syncthreads();
    if (t < 128)
        rowinv[t] = 1.f / (rsp[t][0] + rsp[t][1] + rsp[t][2] + rsp[t][3]
                           + 1.024e-5f);
    __syncthreads();

    float* dst = g_attn + (size_t)nh * LL * HDIM;
    const float* sv = g_sv + nh * 64;
#pragma unroll
    for (int mt = 0; mt < 2; mt++) {
#pragma unroll
        for (int half = 0; half < 2; half++) {
            int r = wm * 32 + mt * 16 + g + half * 8;
            float inv = rowinv[r];
#pragma unroll
            for (int nt = 0; nt < 4; nt++) {
                int d = wn * 32 + nt * 8 + tq * 2;
                *(float2*)(dst + (size_t)(l0 + r) * 64 + d) = make_float2(
                    (D[mt][nt][half * 2 + 0] + 1e-8f * sv[d]) * inv,
                    (D[mt][nt][half * 2 + 1] + 1e-8f * sv[d + 1]) * inv);
            }
        }
    }
}

// ============================================================================
// K5: memory branch, SINGLE-pass fp16 both GEMMs. P scaled by 2^-6 (range).
// ============================================================================
__global__ __launch_bounds__(256, 1) void attn_mem_mma(
    const float* __restrict__ kmem, const float* __restrict__ vmem,
    const float* __restrict__ gatew)
{
    __shared__ unsigned Qf[64][36];
    __shared__ unsigned Kf[32][36];
    __shared__ unsigned Pf[64][20];
    __shared__ unsigned Vt[64][18];
    __shared__ float mask_s[256];
    __shared__ float rs[64][2];

    const int nh = blockIdx.y;
    const int n = nh >> 3, h = nh & 7;
    const int l0 = blockIdx.x * 64;
    const int t = threadIdx.x;
    const int lane = t & 31, warp = t >> 5;
    const int g = lane >> 2, tq = lane & 3;
    const int wm = warp >> 1, wn = warp & 1;

    {   // stage Q fp16 plane (pure copies)
        int r = t >> 2, c = (t & 3) * 8;
        const unsigned* qf = (const unsigned*)g_qf + ((size_t)nh * LL + l0 + r) * 32;
        *(uint4*)&Qf[r][c]     = *(const uint4*)(qf + c);
        *(uint4*)&Qf[r][c + 4] = *(const uint4*)(qf + c + 4);
    }
    mask_s[t] = g_mask[n * MMEM + t] ? 1.f : 0.f;

    float D2[4][4] = {};
    float rsA[2] = {0.f, 0.f};

    const int mr = t >> 3, kq = (t & 7) * 8;

    for (int m0 = 0; m0 < MMEM; m0 += 32) {
        const float* kp = kmem + ((size_t)(m0 + mr) * NBATCH + n) * EDIM + h * 64 + kq;
        const float* vp = vmem + ((size_t)(m0 + mr) * NBATCH + n) * EDIM + h * 64 + kq;
        float4 k0 = *(const float4*)(kp);
        float4 k1 = *(const float4*)(kp + 4);
        float4 v0 = *(const float4*)(vp);
        float4 v1 = *(const float4*)(vp + 4);
        __syncthreads();
        {
            *(uint4*)&Kf[mr][(t & 7) * 4] = make_uint4(
                pack_f16(k0.x, k0.y), pack_f16(k0.z, k0.w),
                pack_f16(k1.x, k1.y), pack_f16(k1.z, k1.w));
            float vv[8] = {v0.x, v0.y, v0.z, v0.w, v1.x, v1.y, v1.z, v1.w};
            unsigned short* pv = (unsigned short*)Vt;
#pragma unroll
            for (int j = 0; j < 8; j++)
                pv[(kq + j) * 36 + mr] =
                    __half_as_ushort(__float2half_rn(vv[j]));
        }
        __syncthreads();

        // GEMM1: sm[64 l][32 m], 1-pass fp16
        float D1[2][4] = {};
#pragma unroll
        for (int ks = 0; ks < 4; ks++) {
            unsigned a[4];
            int m = wm * 16 + g;
            a[0] = Qf[m][ks * 8 + tq];
            a[1] = Qf[m + 8][ks * 8 + tq];
            a[2] = Qf[m][ks * 8 + tq + 4];
            a[3] = Qf[m + 8][ks * 8 + tq + 4];
#pragma unroll
            for (int nt = 0; nt < 2; nt++) {
                int nn = wn * 16 + nt * 8 + g;
                mma_f16(D1[nt], a, Kf[nn][ks * 8 + tq], Kf[nn][ks * 8 + tq + 4]);
            }
        }
        // epilogue: mask + exp * 2^-6, pack fp16, rowsums
#pragma unroll
        for (int nt = 0; nt < 2; nt++) {
            int mcol = wn * 16 + nt * 8 + tq * 2;
            float msk0 = mask_s[m0 + mcol];
            float msk1 = mask_s[m0 + mcol + 1];
#pragma unroll
            for (int half = 0; half < 2; half++) {
                float p0 = (msk0 != 0.f) ? 0.f
                           : __expf(D1[nt][half * 2 + 0]) * 0.015625f;
                float p1 = (msk1 != 0.f) ? 0.f
                           : __expf(D1[nt][half * 2 + 1]) * 0.015625f;
                rsA[half] += p0 + p1;
                int row = wm * 16 + g + half * 8;
                Pf[row][wn * 8 + nt * 4 + tq] = pack_f16(p0, p1);
            }
        }
        __syncthreads();

        // GEMM2: O[64 l][64 d] += P @ Vt, 1-pass fp16, k=32
#pragma unroll
        for (int ks = 0; ks < 2; ks++) {
            unsigned a[4];
            int m = wm * 16 + g;
            a[0] = Pf[m][ks * 8 + tq];
            a[1] = Pf[m + 8][ks * 8 + tq];
            a[2] = Pf[m][ks * 8 + tq + 4];
            a[3] = Pf[m + 8][ks * 8 + tq + 4];
#pragma unroll
            for (int nt = 0; nt < 4; nt++) {
                int nn = wn * 32 + nt * 8 + g;
                mma_f16(D2[nt], a, Vt[nn][ks * 8 + tq], Vt[nn][ks * 8 + tq + 4]);
            }
        }
    }

    float r0 = rsA[0], r1 = rsA[1];
    r0 += __shfl_xor_sync(0xffffffffu, r0, 1);
    r0 += __shfl_xor_sync(0xffffffffu, r0, 2);
    r1 += __shfl_xor_sync(0xffffffffu, r1, 1);
    r1 += __shfl_xor_sync(0xffffffffu, r1, 2);
    __syncthreads();
    if (tq == 0) {
        rs[wm * 16 + g][wn]     = r0;
        rs[wm * 16 + g + 8][wn] = r1;
    }
    __syncthreads();

    const float gate = 1.f / (1.f + __expf(-gatew[h]));
    const float omg = 1.f - gate;
#pragma unroll
    for (int half = 0; half < 2; half++) {
        int rl = wm * 16 + g + half * 8;
        int l = l0 + rl;
        float inv = 1.f / (rs[rl][0] + rs[rl][1]);
#pragma unroll
        for (int nt = 0; nt < 4; nt++) {
            int d = wn * 32 + nt * 8 + tq * 2;
            float2 am = *(const float2*)(g_attn + ((size_t)nh * LL + l) * 64 + d);
            float o0 = gate * (D2[nt][half * 2 + 0] * inv) + omg * am.x;
            float o1 = gate * (D2[nt][half * 2 + 1] * inv) + omg * am.y;
            unsigned hi, lo;
            split2(o0, o1, hi, lo);
            size_t ui = (((size_t)l * NBATCH + n) * EDIM + h * 64 + d) >> 1;
            ((unsigned*)g_ctxh)[ui] = hi;
            ((unsigned*)g_ctxl)[ui] = lo;
        }
    }
}

// ============================================================================
extern "C" void kernel_launch(void* const* d_in, const int* in_sizes, int n_in,
                              void* d_out, int out_size)
{
    const float* query = (const float*)d_in[0];
    const float* key   = (const float*)d_in[1];
    const float* value = (const float*)d_in[2];
    const float* Wi    = (const float*)d_in[3];
    const float* Bi    = (const float*)d_in[4];
    const float* Wo    = (const float*)d_in[5];
    const float* Bo    = (const float*)d_in[6];
    const float* rq    = (const float*)d_in[7];
    const float* rk    = (const float*)d_in[8];
    const float* kmem  = (const float*)d_in[9];
    const float* vmem  = (const float*)d_in[10];
    const float* gate  = (const float*)d_in[11];
    const unsigned int* mmask_raw = (const unsigned int*)d_in[12];
    float* out = (float*)d_out;

    const int NX2 = RTOT * EDIM / 2;
    const int NW2 = 3 * EDIM * EDIM / 2;
    const int NWO2 = EDIM * EDIM / 2;

    mask_decode_kernel<<<1, 256>>>(mmask_raw);
    split_kernel<<<2048, 256>>>(query, 0, 0, NX2);
    split_kernel<<<2048, 256>>>(key,   0, (size_t)RTOT * EDIM, NX2);
    split_kernel<<<2048, 256>>>(value, 0, (size_t)2 * RTOT * EDIM, NX2);
    split_kernel<<<1024, 256>>>(Wi, 1, 0, NW2);
    split_kernel<<<512, 256>>>(Wo, 1, (size_t)3 * EDIM * EDIM, NWO2);

    proj_mma<<<dim3(4, 64, 3), 256>>>(Bi, Bo, rq, rk, out, 0);
    vsum_kernel<<<64, 256>>>();
    scores_mma<<<dim3(8, 8, 64), 256>>>();
    colsum2_kernel<<<dim3(4, 64), 256>>>();
    attn_main_mma<<<dim3(8, 64), 256>>>();
    attn_mem_mma<<<dim3(16, 64), 256>>>(kmem, vmem, gate);
    proj_mma<<<dim3(4, 64, 1), 256>>>(Bi, Bo, rq, rk, out, 3);
}